// round 1
// baseline (speedup 1.0000x reference)
#include <cuda_runtime.h>
#include <math.h>

// Problem constants
#define L 8192
#define H 128
#define NC 4
#define KS 7

// ---------------- scratch (static device memory; no runtime allocation) ----------------
__device__ float g_h [L*H];          // running hidden state
__device__ float g_n [L*H];          // layernorm output
__device__ float g_q [L*H];
__device__ float g_k [L*H];
__device__ float g_v [L*H];
__device__ float g_vt[L*H];          // V transposed [H][L]
__device__ float g_wT[NC*KS*H*H];    // conv weights as [ic][k][c][o]
__device__ float g_S [67108864];     // attention scores [L][L] (256 MB)

// ---------------- positional encoding + add ----------------
__global__ void posenc_kernel(const float* __restrict__ x, float* __restrict__ h) {
    int idx = blockIdx.x * 256 + threadIdx.x;          // exactly L*H threads
    int l = idx >> 7, i = idx & 127;
    float di = (float)((i >> 1) << 1);                 // 2*floor(i/2)
    float denom = powf(10000.0f, di * (1.0f / 128.0f));
    float ang = (float)l / denom;
    float pe = (i & 1) ? cosf(ang) : sinf(ang);
    h[idx] = x[idx] + pe;
}

// ---------------- layernorm: one warp per row (H=128 -> 4 floats/lane) ----------------
__global__ void ln_kernel(const float* __restrict__ in, float* __restrict__ out) {
    int warp = threadIdx.x >> 5, lane = threadIdx.x & 31;
    int row = blockIdx.x * 8 + warp;
    const float4* ip = reinterpret_cast<const float4*>(in + (size_t)row * H);
    float4 v = ip[lane];
    float s = v.x + v.y + v.z + v.w;
    float q = v.x*v.x + v.y*v.y + v.z*v.z + v.w*v.w;
#pragma unroll
    for (int o = 16; o > 0; o >>= 1) {
        s += __shfl_xor_sync(0xffffffffu, s, o);
        q += __shfl_xor_sync(0xffffffffu, q, o);
    }
    float mu  = s * (1.0f / H);
    float var = q * (1.0f / H) - mu * mu;
    float inv = rsqrtf(var + 1e-5f);
    float4 o4 = make_float4((v.x-mu)*inv, (v.y-mu)*inv, (v.z-mu)*inv, (v.w-mu)*inv);
    reinterpret_cast<float4*>(out + (size_t)row * H)[lane] = o4;
}

// ---------------- conv weight transpose: w[ic][o][c][k] -> wT[ic][k][c][o] ----------------
__global__ void prep_w_kernel(const float* __restrict__ w, float* __restrict__ wT) {
    int idx = blockIdx.x * 256 + threadIdx.x;          // NC*KS*H*H = 458752
    int o  = idx & 127;
    int r  = idx >> 7;
    int c  = r & 127;
    int r2 = r >> 7;
    int k  = r2 % 7;
    int ic = r2 / 7;
    wT[idx] = w[(((size_t)ic * H + o) * H + c) * KS + k];
}

// ---------------- conv1d SAME (K=7) + bias + residual (in-place on h) ----------------
// block = 32 rows, 256 threads: thread -> (o = t&127, row group rg = t>>7 of 16 rows)
__global__ __launch_bounds__(256) void conv_kernel(
    const float* __restrict__ nin, const float* __restrict__ wT,
    const float* __restrict__ bias, float* __restrict__ h)
{
    __shared__ float sIn[38 * 128];                    // rows r0-3 .. r0+34
    int t = threadIdx.x;
    int r0 = blockIdx.x * 32;
    for (int it = t; it < 38 * 32; it += 256) {
        int rl = it >> 5, c4 = it & 31;
        int gr = r0 - 3 + rl;
        float4 vv = make_float4(0.f, 0.f, 0.f, 0.f);
        if (gr >= 0 && gr < L)
            vv = reinterpret_cast<const float4*>(nin)[(size_t)gr * 32 + c4];
        reinterpret_cast<float4*>(sIn)[rl * 32 + c4] = vv;
    }
    __syncthreads();

    int o = t & 127, rg = t >> 7;
    int rbase = rg * 16;
    float acc[16];
#pragma unroll
    for (int r = 0; r < 16; r++) acc[r] = 0.f;

    for (int c = 0; c < 128; c++) {
        float xv[22];
#pragma unroll
        for (int j = 0; j < 22; j++) xv[j] = sIn[(rbase + j) * 128 + c];  // broadcast, CF
#pragma unroll
        for (int k = 0; k < 7; k++) {
            float wv = wT[((k << 7) + c) * 128 + o];                      // coalesced
#pragma unroll
            for (int r = 0; r < 16; r++) acc[r] = fmaf(wv, xv[r + k], acc[r]);
        }
    }
    float b = bias[o];
#pragma unroll
    for (int r = 0; r < 16; r++) {
        size_t gi = (size_t)(r0 + rbase + r) * H + o;
        h[gi] += acc[r] + b;
    }
}

// ---------------- generic NT GEMM: C[m][n] = scale * sum_c A[m][c]*B[n][c] (+bias,+relu,+resid) ----------------
// tiles 64x64x32, 256 threads, 4x4 microtile, warp shaped 4x8 -> conflict-free frag loads
__global__ __launch_bounds__(256) void gemm_nt_kernel(
    const float* __restrict__ A, const float* __restrict__ B,
    const float* __restrict__ bias, const float* __restrict__ resid,
    float* __restrict__ C, int M, int N, int K, float scale, int do_relu)
{
    __shared__ float sA[64][33];
    __shared__ float sB[64][33];
    int t = threadIdx.x;
    int m0 = blockIdx.y << 6, n0 = blockIdx.x << 6;
    int warp = t >> 5, lane = t & 31;
    int ty = ((warp & 3) << 2) + (lane >> 3);   // 0..15
    int tx = ((warp >> 2) << 3) + (lane & 7);   // 0..15
    int row = ty << 2, col = tx << 2;

    float acc[4][4];
#pragma unroll
    for (int i = 0; i < 4; i++)
#pragma unroll
        for (int j = 0; j < 4; j++) acc[i][j] = 0.f;

    int lr = t >> 3;               // 0..31
    int lc = (t & 7) << 2;         // 0,4,...,28

    for (int k0 = 0; k0 < K; k0 += 32) {
#pragma unroll
        for (int it = 0; it < 2; it++) {
            int r = lr + it * 32;
            float4 va = *reinterpret_cast<const float4*>(A + (size_t)(m0 + r) * K + k0 + lc);
            sA[r][lc+0] = va.x; sA[r][lc+1] = va.y; sA[r][lc+2] = va.z; sA[r][lc+3] = va.w;
            float4 vb = *reinterpret_cast<const float4*>(B + (size_t)(n0 + r) * K + k0 + lc);
            sB[r][lc+0] = vb.x; sB[r][lc+1] = vb.y; sB[r][lc+2] = vb.z; sB[r][lc+3] = vb.w;
        }
        __syncthreads();
#pragma unroll 8
        for (int kk = 0; kk < 32; kk++) {
            float a0 = sA[row+0][kk], a1 = sA[row+1][kk], a2 = sA[row+2][kk], a3 = sA[row+3][kk];
            float b0 = sB[col+0][kk], b1 = sB[col+1][kk], b2 = sB[col+2][kk], b3 = sB[col+3][kk];
            acc[0][0] = fmaf(a0,b0,acc[0][0]); acc[0][1] = fmaf(a0,b1,acc[0][1]);
            acc[0][2] = fmaf(a0,b2,acc[0][2]); acc[0][3] = fmaf(a0,b3,acc[0][3]);
            acc[1][0] = fmaf(a1,b0,acc[1][0]); acc[1][1] = fmaf(a1,b1,acc[1][1]);
            acc[1][2] = fmaf(a1,b2,acc[1][2]); acc[1][3] = fmaf(a1,b3,acc[1][3]);
            acc[2][0] = fmaf(a2,b0,acc[2][0]); acc[2][1] = fmaf(a2,b1,acc[2][1]);
            acc[2][2] = fmaf(a2,b2,acc[2][2]); acc[2][3] = fmaf(a2,b3,acc[2][3]);
            acc[3][0] = fmaf(a3,b0,acc[3][0]); acc[3][1] = fmaf(a3,b1,acc[3][1]);
            acc[3][2] = fmaf(a3,b2,acc[3][2]); acc[3][3] = fmaf(a3,b3,acc[3][3]);
        }
        __syncthreads();
    }

    float bv[4] = {0.f, 0.f, 0.f, 0.f};
    if (bias) {
        bv[0] = bias[n0+col+0]; bv[1] = bias[n0+col+1];
        bv[2] = bias[n0+col+2]; bv[3] = bias[n0+col+3];
    }
#pragma unroll
    for (int i = 0; i < 4; i++) {
        size_t ci = (size_t)(m0 + row + i) * N + n0 + col;
        float4 r4 = make_float4(0.f, 0.f, 0.f, 0.f);
        if (resid) r4 = *reinterpret_cast<const float4*>(resid + ci);
        float v0 = acc[i][0] * scale + bv[0];
        float v1 = acc[i][1] * scale + bv[1];
        float v2 = acc[i][2] * scale + bv[2];
        float v3 = acc[i][3] * scale + bv[3];
        if (do_relu) {
            v0 = fmaxf(v0, 0.f); v1 = fmaxf(v1, 0.f);
            v2 = fmaxf(v2, 0.f); v3 = fmaxf(v3, 0.f);
        }
        v0 += r4.x; v1 += r4.y; v2 += r4.z; v3 += r4.w;
        *reinterpret_cast<float4*>(C + ci) = make_float4(v0, v1, v2, v3);
    }
}

// ---------------- row softmax over 8192 (in place) ----------------
__global__ __launch_bounds__(256) void softmax_kernel(float* __restrict__ S) {
    __shared__ float red[8];
    int t = threadIdx.x;
    int warp = t >> 5, lane = t & 31;
    float4* rp = reinterpret_cast<float4*>(S + (size_t)blockIdx.x * L);
    float4 v[8];
    float mx = -3.4e38f;
#pragma unroll
    for (int i = 0; i < 8; i++) {
        v[i] = rp[t + (i << 8)];
        mx = fmaxf(mx, fmaxf(fmaxf(v[i].x, v[i].y), fmaxf(v[i].z, v[i].w)));
    }
#pragma unroll
    for (int o = 16; o > 0; o >>= 1) mx = fmaxf(mx, __shfl_xor_sync(0xffffffffu, mx, o));
    if (lane == 0) red[warp] = mx;
    __syncthreads();
    mx = red[0];
#pragma unroll
    for (int i = 1; i < 8; i++) mx = fmaxf(mx, red[i]);
    __syncthreads();

    float sum = 0.f;
#pragma unroll
    for (int i = 0; i < 8; i++) {
        v[i].x = expf(v[i].x - mx); v[i].y = expf(v[i].y - mx);
        v[i].z = expf(v[i].z - mx); v[i].w = expf(v[i].w - mx);
        sum += (v[i].x + v[i].y) + (v[i].z + v[i].w);
    }
#pragma unroll
    for (int o = 16; o > 0; o >>= 1) sum += __shfl_xor_sync(0xffffffffu, sum, o);
    if (lane == 0) red[warp] = sum;
    __syncthreads();
    sum = 0.f;
#pragma unroll
    for (int i = 0; i < 8; i++) sum += red[i];
    float inv = 1.0f / sum;
#pragma unroll
    for (int i = 0; i < 8; i++) {
        v[i].x *= inv; v[i].y *= inv; v[i].z *= inv; v[i].w *= inv;
        rp[t + (i << 8)] = v[i];
    }
}

// ---------------- V transpose [L][H] -> [H][L] ----------------
__global__ void transpose_kernel(const float* __restrict__ in, float* __restrict__ out) {
    __shared__ float tile[32][33];
    int j0 = blockIdx.x * 32, d0 = blockIdx.y * 32;
    int tx = threadIdx.x, ty = threadIdx.y;
#pragma unroll
    for (int i = 0; i < 4; i++) {
        int jj = ty + i * 8;
        tile[jj][tx] = in[(size_t)(j0 + jj) * H + d0 + tx];
    }
    __syncthreads();
#pragma unroll
    for (int i = 0; i < 4; i++) {
        int dd = ty + i * 8;
        out[(size_t)(d0 + dd) * L + j0 + tx] = tile[tx][dd];
    }
}

// ---------------- launch ----------------
extern "C" void kernel_launch(void* const* d_in, const int* in_sizes, int n_in,
                              void* d_out, int out_size) {
    const float* x      = (const float*)d_in[0];
    const float* conv_w = (const float*)d_in[1];
    const float* conv_b = (const float*)d_in[2];
    const float* Wq     = (const float*)d_in[3];
    const float* bq     = (const float*)d_in[4];
    const float* Wk     = (const float*)d_in[5];
    const float* bk     = (const float*)d_in[6];
    const float* Wv     = (const float*)d_in[7];
    const float* bv     = (const float*)d_in[8];
    const float* Wff    = (const float*)d_in[9];
    const float* bff    = (const float*)d_in[10];
    float* out = (float*)d_out;

    float *p_h, *p_n, *p_q, *p_k, *p_v, *p_vt, *p_wT, *p_S;
    cudaGetSymbolAddress((void**)&p_h,  g_h);
    cudaGetSymbolAddress((void**)&p_n,  g_n);
    cudaGetSymbolAddress((void**)&p_q,  g_q);
    cudaGetSymbolAddress((void**)&p_k,  g_k);
    cudaGetSymbolAddress((void**)&p_v,  g_v);
    cudaGetSymbolAddress((void**)&p_vt, g_vt);
    cudaGetSymbolAddress((void**)&p_wT, g_wT);
    cudaGetSymbolAddress((void**)&p_S,  g_S);

    const float scale = 0.08838834764831845f;  // 1/sqrt(128)

    prep_w_kernel<<<1792, 256>>>(conv_w, p_wT);
    posenc_kernel<<<4096, 256>>>(x, p_h);

    for (int ic = 0; ic < NC; ic++) {
        ln_kernel<<<1024, 256>>>(p_h, p_n);
        conv_kernel<<<256, 256>>>(p_n, p_wT + (size_t)ic * KS * H * H,
                                  conv_b + ic * H, p_h);
    }

    // attention
    ln_kernel<<<1024, 256>>>(p_h, p_n);
    gemm_nt_kernel<<<dim3(2, 128), 256>>>(p_n, Wq, bq, nullptr, p_q, L, H, H, 1.f, 0);
    gemm_nt_kernel<<<dim3(2, 128), 256>>>(p_n, Wk, bk, nullptr, p_k, L, H, H, 1.f, 0);
    gemm_nt_kernel<<<dim3(2, 128), 256>>>(p_n, Wv, bv, nullptr, p_v, L, H, H, 1.f, 0);
    gemm_nt_kernel<<<dim3(128, 128), 256>>>(p_q, p_k, nullptr, nullptr, p_S, L, L, H, scale, 0);
    softmax_kernel<<<L, 256>>>(p_S);
    transpose_kernel<<<dim3(256, 4), dim3(32, 8)>>>(p_v, p_vt);
    gemm_nt_kernel<<<dim3(2, 128), 256>>>(p_S, p_vt, nullptr, p_h, p_h, L, H, L, 1.f, 0);

    // feed-forward
    ln_kernel<<<1024, 256>>>(p_h, p_n);
    gemm_nt_kernel<<<dim3(2, 128), 256>>>(p_n, Wff, bff, p_h, out, L, H, H, 1.f, 1);
}

// round 2
// speedup vs baseline: 2.8926x; 2.8926x over previous
#include <cuda_runtime.h>
#include <cuda_bf16.h>
#include <math.h>
#include <stdint.h>

#define L 8192
#define H 128
#define NC 4
#define KS 7
#define LH (L*H)

// ---------------- scratch (static device memory) ----------------
__device__ float g_h [LH];
__device__ float g_n [LH];
__device__ float g_v [LH];
__device__ float g_part[4*LH];            // split-K partials for PV
__device__ float g_wT[NC*KS*H*H];         // conv weights [ic][k][c][o]
__device__ float g_S [ (size_t)L*L ];     // attention logits fp32 (256MB)
__device__ __nv_bfloat16 g_qb[LH];
__device__ __nv_bfloat16 g_kb[LH];
__device__ __nv_bfloat16 g_vtb[LH];       // V^T [H][L] bf16
__device__ __nv_bfloat16 g_P [ (size_t)L*L ];  // softmax probs bf16 (128MB)

// ---------------- positional encoding + add ----------------
__global__ void posenc_kernel(const float* __restrict__ x, float* __restrict__ h) {
    int idx = blockIdx.x * 256 + threadIdx.x;
    int l = idx >> 7, i = idx & 127;
    float di = (float)((i >> 1) << 1);
    float denom = powf(10000.0f, di * (1.0f / 128.0f));
    float ang = (float)l / denom;
    float pe = (i & 1) ? cosf(ang) : sinf(ang);
    h[idx] = x[idx] + pe;
}

// ---------------- layernorm: one warp per row ----------------
__global__ void ln_kernel(const float* __restrict__ in, float* __restrict__ out) {
    int warp = threadIdx.x >> 5, lane = threadIdx.x & 31;
    int row = blockIdx.x * 8 + warp;
    const float4* ip = reinterpret_cast<const float4*>(in + (size_t)row * H);
    float4 v = ip[lane];
    float s = v.x + v.y + v.z + v.w;
    float q = v.x*v.x + v.y*v.y + v.z*v.z + v.w*v.w;
#pragma unroll
    for (int o = 16; o > 0; o >>= 1) {
        s += __shfl_xor_sync(0xffffffffu, s, o);
        q += __shfl_xor_sync(0xffffffffu, q, o);
    }
    float mu  = s * (1.0f / H);
    float var = q * (1.0f / H) - mu * mu;
    float inv = rsqrtf(var + 1e-5f);
    float4 o4 = make_float4((v.x-mu)*inv, (v.y-mu)*inv, (v.z-mu)*inv, (v.w-mu)*inv);
    reinterpret_cast<float4*>(out + (size_t)row * H)[lane] = o4;
}

// ---------------- conv weight transpose ----------------
__global__ void prep_w_kernel(const float* __restrict__ w, float* __restrict__ wT) {
    int idx = blockIdx.x * 256 + threadIdx.x;
    int o  = idx & 127;
    int r  = idx >> 7;
    int c  = r & 127;
    int r2 = r >> 7;
    int k  = r2 % 7;
    int ic = r2 / 7;
    wT[idx] = w[(((size_t)ic * H + o) * H + c) * KS + k];
}

// ---------------- conv1d SAME (K=7) + bias + residual ----------------
__global__ __launch_bounds__(256) void conv_kernel(
    const float* __restrict__ nin, const float* __restrict__ wT,
    const float* __restrict__ bias, float* __restrict__ h)
{
    __shared__ float sIn[38 * 128];
    int t = threadIdx.x;
    int r0 = blockIdx.x * 32;
    for (int it = t; it < 38 * 32; it += 256) {
        int rl = it >> 5, c4 = it & 31;
        int gr = r0 - 3 + rl;
        float4 vv = make_float4(0.f, 0.f, 0.f, 0.f);
        if (gr >= 0 && gr < L)
            vv = reinterpret_cast<const float4*>(nin)[(size_t)gr * 32 + c4];
        reinterpret_cast<float4*>(sIn)[rl * 32 + c4] = vv;
    }
    __syncthreads();

    int o = t & 127, rg = t >> 7;
    int rbase = rg * 16;
    float acc[16];
#pragma unroll
    for (int r = 0; r < 16; r++) acc[r] = 0.f;

    const float* wp = wT + o;
    float wv[7];
#pragma unroll
    for (int k = 0; k < 7; k++) wv[k] = wp[(size_t)((k << 7)) * 128];

    for (int c = 0; c < 128; c++) {
        int cn = (c + 1 < 128) ? c + 1 : 127;
        float wnx[7];
#pragma unroll
        for (int k = 0; k < 7; k++) wnx[k] = wp[(size_t)((k << 7) + cn) * 128];
        float xv[22];
#pragma unroll
        for (int j = 0; j < 22; j++) xv[j] = sIn[(rbase + j) * 128 + c];
#pragma unroll
        for (int k = 0; k < 7; k++) {
#pragma unroll
            for (int r = 0; r < 16; r++) acc[r] = fmaf(wv[k], xv[r + k], acc[r]);
        }
#pragma unroll
        for (int k = 0; k < 7; k++) wv[k] = wnx[k];
    }
    float b = bias[o];
#pragma unroll
    for (int r = 0; r < 16; r++) {
        size_t gi = (size_t)(r0 + rbase + r) * H + o;
        h[gi] += acc[r] + b;
    }
}

// ---------------- fp32 NT GEMM (small: QKV/FF projections) ----------------
// C = (A·B^T + bias) * scale ; optional relu ; + resid ; out fp32 or bf16
__global__ __launch_bounds__(256) void gemm_nt_kernel(
    const float* __restrict__ A, const float* __restrict__ B,
    const float* __restrict__ bias, const float* __restrict__ resid,
    void* __restrict__ Cout, int M, int N, int K, float scale,
    int do_relu, int out_bf16)
{
    __shared__ float sA[64][33];
    __shared__ float sB[64][33];
    int t = threadIdx.x;
    int m0 = blockIdx.y << 6, n0 = blockIdx.x << 6;
    int warp = t >> 5, lane = t & 31;
    int ty = ((warp & 3) << 2) + (lane >> 3);
    int tx = ((warp >> 2) << 3) + (lane & 7);
    int row = ty << 2, col = tx << 2;

    float acc[4][4];
#pragma unroll
    for (int i = 0; i < 4; i++)
#pragma unroll
        for (int j = 0; j < 4; j++) acc[i][j] = 0.f;

    int lr = t >> 3;
    int lc = (t & 7) << 2;

    for (int k0 = 0; k0 < K; k0 += 32) {
#pragma unroll
        for (int it = 0; it < 2; it++) {
            int r = lr + it * 32;
            float4 va = *reinterpret_cast<const float4*>(A + (size_t)(m0 + r) * K + k0 + lc);
            sA[r][lc+0] = va.x; sA[r][lc+1] = va.y; sA[r][lc+2] = va.z; sA[r][lc+3] = va.w;
            float4 vb = *reinterpret_cast<const float4*>(B + (size_t)(n0 + r) * K + k0 + lc);
            sB[r][lc+0] = vb.x; sB[r][lc+1] = vb.y; sB[r][lc+2] = vb.z; sB[r][lc+3] = vb.w;
        }
        __syncthreads();
#pragma unroll 8
        for (int kk = 0; kk < 32; kk++) {
            float a0 = sA[row+0][kk], a1 = sA[row+1][kk], a2 = sA[row+2][kk], a3 = sA[row+3][kk];
            float b0 = sB[col+0][kk], b1 = sB[col+1][kk], b2 = sB[col+2][kk], b3 = sB[col+3][kk];
            acc[0][0] = fmaf(a0,b0,acc[0][0]); acc[0][1] = fmaf(a0,b1,acc[0][1]);
            acc[0][2] = fmaf(a0,b2,acc[0][2]); acc[0][3] = fmaf(a0,b3,acc[0][3]);
            acc[1][0] = fmaf(a1,b0,acc[1][0]); acc[1][1] = fmaf(a1,b1,acc[1][1]);
            acc[1][2] = fmaf(a1,b2,acc[1][2]); acc[1][3] = fmaf(a1,b3,acc[1][3]);
            acc[2][0] = fmaf(a2,b0,acc[2][0]); acc[2][1] = fmaf(a2,b1,acc[2][1]);
            acc[2][2] = fmaf(a2,b2,acc[2][2]); acc[2][3] = fmaf(a2,b3,acc[2][3]);
            acc[3][0] = fmaf(a3,b0,acc[3][0]); acc[3][1] = fmaf(a3,b1,acc[3][1]);
            acc[3][2] = fmaf(a3,b2,acc[3][2]); acc[3][3] = fmaf(a3,b3,acc[3][3]);
        }
        __syncthreads();
    }

    float bv[4] = {0.f, 0.f, 0.f, 0.f};
    if (bias) {
        bv[0] = bias[n0+col+0]; bv[1] = bias[n0+col+1];
        bv[2] = bias[n0+col+2]; bv[3] = bias[n0+col+3];
    }
#pragma unroll
    for (int i = 0; i < 4; i++) {
        size_t ci = (size_t)(m0 + row + i) * N + n0 + col;
        float4 r4 = make_float4(0.f, 0.f, 0.f, 0.f);
        if (resid) r4 = *reinterpret_cast<const float4*>(resid + ci);
        float v0 = (acc[i][0] + bv[0]) * scale;
        float v1 = (acc[i][1] + bv[1]) * scale;
        float v2 = (acc[i][2] + bv[2]) * scale;
        float v3 = (acc[i][3] + bv[3]) * scale;
        if (do_relu) {
            v0 = fmaxf(v0, 0.f); v1 = fmaxf(v1, 0.f);
            v2 = fmaxf(v2, 0.f); v3 = fmaxf(v3, 0.f);
        }
        v0 += r4.x; v1 += r4.y; v2 += r4.z; v3 += r4.w;
        if (out_bf16) {
            __nv_bfloat162 p0 = __floats2bfloat162_rn(v0, v1);
            __nv_bfloat162 p1 = __floats2bfloat162_rn(v2, v3);
            uint2 pk; pk.x = *reinterpret_cast<uint32_t*>(&p0); pk.y = *reinterpret_cast<uint32_t*>(&p1);
            *reinterpret_cast<uint2*>((__nv_bfloat16*)Cout + ci) = pk;
        } else {
            *reinterpret_cast<float4*>((float*)Cout + ci) = make_float4(v0, v1, v2, v3);
        }
    }
}

// ---------------- bf16 tensor-core NT GEMM ----------------
// C[m][n] = sum_k A[m][k]*B[n][k], 128x128 tile, K-chunk 64, 2-stage cp.async
__device__ __forceinline__ void cp16(uint32_t dst, const void* src) {
    asm volatile("cp.async.cg.shared.global [%0], [%1], 16;\n" :: "r"(dst), "l"(src));
}
__device__ __forceinline__ void ldsm4(uint32_t* r, uint32_t addr) {
    asm volatile("ldmatrix.sync.aligned.m8n8.x4.shared.b16 {%0,%1,%2,%3}, [%4];"
        : "=r"(r[0]), "=r"(r[1]), "=r"(r[2]), "=r"(r[3]) : "r"(addr));
}
__device__ __forceinline__ void mma16816(float* c, const uint32_t* a, uint32_t b0, uint32_t b1) {
    asm volatile("mma.sync.aligned.m16n8k16.row.col.f32.bf16.bf16.f32 "
        "{%0,%1,%2,%3}, {%4,%5,%6,%7}, {%8,%9}, {%0,%1,%2,%3};"
        : "+f"(c[0]), "+f"(c[1]), "+f"(c[2]), "+f"(c[3])
        : "r"(a[0]), "r"(a[1]), "r"(a[2]), "r"(a[3]), "r"(b0), "r"(b1));
}

#define STAGE_BYTES 32768   // 16KB A + 16KB B

__device__ __forceinline__ void load_stage_tc(
    const __nv_bfloat16* At, int ldA, const __nv_bfloat16* Bt, int ldB,
    uint32_t sbase, int t)
{
#pragma unroll
    for (int i = 0; i < 4; i++) {
        int idx = t + (i << 8);
        int row = idx >> 3, ch = idx & 7;
        uint32_t dst = sbase + row * 128 + ((ch ^ (row & 7)) << 4);
        cp16(dst, At + (size_t)row * ldA + (ch << 3));
    }
#pragma unroll
    for (int i = 0; i < 4; i++) {
        int idx = t + (i << 8);
        int row = idx >> 3, ch = idx & 7;
        uint32_t dst = sbase + 16384 + row * 128 + ((ch ^ (row & 7)) << 4);
        cp16(dst, Bt + (size_t)row * ldB + (ch << 3));
    }
}

__global__ __launch_bounds__(256) void gemm_bf16_tc(
    const __nv_bfloat16* __restrict__ A, int ldA,
    const __nv_bfloat16* __restrict__ B, int ldB,
    float* __restrict__ C, int ldC, int Klen, size_t cSliceStride)
{
    extern __shared__ __align__(128) char smem[];
    uint32_t sbase = (uint32_t)__cvta_generic_to_shared(smem);
    int t = threadIdx.x;
    int m0 = blockIdx.y << 7, n0 = blockIdx.x << 7;
    size_t koff = (size_t)blockIdx.z * Klen;
    A += (size_t)m0 * ldA + koff;
    B += (size_t)n0 * ldB + koff;
    C += (size_t)blockIdx.z * cSliceStride;

    int warp = t >> 5, lane = t & 31;
    int wm = warp >> 1, wn = warp & 1;

    float acc[2][8][4];
#pragma unroll
    for (int mt = 0; mt < 2; mt++)
#pragma unroll
        for (int nt = 0; nt < 8; nt++)
#pragma unroll
            for (int i = 0; i < 4; i++) acc[mt][nt][i] = 0.f;

    int nCh = Klen >> 6;
    load_stage_tc(A, ldA, B, ldB, sbase, t);
    asm volatile("cp.async.commit_group;\n");

    for (int c = 0; c < nCh; c++) {
        if (c + 1 < nCh) {
            load_stage_tc(A + ((c + 1) << 6), ldA, B + ((c + 1) << 6), ldB,
                          sbase + ((c + 1) & 1) * STAGE_BYTES, t);
            asm volatile("cp.async.commit_group;\n");
            asm volatile("cp.async.wait_group 1;\n");
        } else {
            asm volatile("cp.async.wait_group 0;\n");
        }
        __syncthreads();

        uint32_t aB = sbase + (c & 1) * STAGE_BYTES;
        uint32_t bB = aB + 16384;
#pragma unroll
        for (int k16 = 0; k16 < 4; k16++) {
            uint32_t afr[2][4];
#pragma unroll
            for (int mt = 0; mt < 2; mt++) {
                int row = (wm << 5) + (mt << 4) + (lane & 7) + (((lane >> 3) & 1) << 3);
                int ch  = (k16 << 1) + ((lane >> 4) & 1);
                ldsm4(afr[mt], aB + row * 128 + ((ch ^ (row & 7)) << 4));
            }
            uint32_t bfr[4][4];
#pragma unroll
            for (int np = 0; np < 4; np++) {
                int row = (wn << 6) + (np << 4) + (lane & 7) + ((lane >> 4) << 3);
                int ch  = (k16 << 1) + ((lane >> 3) & 1);
                ldsm4(bfr[np], bB + row * 128 + ((ch ^ (row & 7)) << 4));
            }
#pragma unroll
            for (int mt = 0; mt < 2; mt++)
#pragma unroll
                for (int nt = 0; nt < 8; nt++)
                    mma16816(acc[mt][nt], afr[mt],
                             bfr[nt >> 1][(nt & 1) << 1], bfr[nt >> 1][((nt & 1) << 1) + 1]);
        }
        __syncthreads();
    }

    // epilogue
    int g = lane >> 2, tq = lane & 3;
#pragma unroll
    for (int mt = 0; mt < 2; mt++) {
#pragma unroll
        for (int nt = 0; nt < 8; nt++) {
            int r = m0 + (wm << 5) + (mt << 4) + g;
            int cc = n0 + (wn << 6) + (nt << 3) + (tq << 1);
            float2 v0 = make_float2(acc[mt][nt][0], acc[mt][nt][1]);
            float2 v1 = make_float2(acc[mt][nt][2], acc[mt][nt][3]);
            *reinterpret_cast<float2*>(C + (size_t)r * ldC + cc) = v0;
            *reinterpret_cast<float2*>(C + (size_t)(r + 8) * ldC + cc) = v1;
        }
    }
}

// ---------------- row softmax fp32 -> bf16 ----------------
__global__ __launch_bounds__(256) void softmax_kernel(const float* __restrict__ S,
                                                      __nv_bfloat16* __restrict__ P) {
    __shared__ float red[8];
    int t = threadIdx.x;
    int warp = t >> 5, lane = t & 31;
    const float4* rp = reinterpret_cast<const float4*>(S + (size_t)blockIdx.x * L);
    uint2* wp = reinterpret_cast<uint2*>(P + (size_t)blockIdx.x * L);
    float4 v[8];
    float mx = -3.4e38f;
#pragma unroll
    for (int i = 0; i < 8; i++) {
        v[i] = rp[t + (i << 8)];
        mx = fmaxf(mx, fmaxf(fmaxf(v[i].x, v[i].y), fmaxf(v[i].z, v[i].w)));
    }
#pragma unroll
    for (int o = 16; o > 0; o >>= 1) mx = fmaxf(mx, __shfl_xor_sync(0xffffffffu, mx, o));
    if (lane == 0) red[warp] = mx;
    __syncthreads();
    mx = red[0];
#pragma unroll
    for (int i = 1; i < 8; i++) mx = fmaxf(mx, red[i]);
    __syncthreads();

    float sum = 0.f;
#pragma unroll
    for (int i = 0; i < 8; i++) {
        v[i].x = expf(v[i].x - mx); v[i].y = expf(v[i].y - mx);
        v[i].z = expf(v[i].z - mx); v[i].w = expf(v[i].w - mx);
        sum += (v[i].x + v[i].y) + (v[i].z + v[i].w);
    }
#pragma unroll
    for (int o = 16; o > 0; o >>= 1) sum += __shfl_xor_sync(0xffffffffu, sum, o);
    if (lane == 0) red[warp] = sum;
    __syncthreads();
    sum = 0.f;
#pragma unroll
    for (int i = 0; i < 8; i++) sum += red[i];
    float inv = 1.0f / sum;
#pragma unroll
    for (int i = 0; i < 8; i++) {
        __nv_bfloat162 p0 = __floats2bfloat162_rn(v[i].x * inv, v[i].y * inv);
        __nv_bfloat162 p1 = __floats2bfloat162_rn(v[i].z * inv, v[i].w * inv);
        uint2 pk; pk.x = *reinterpret_cast<uint32_t*>(&p0); pk.y = *reinterpret_cast<uint32_t*>(&p1);
        wp[t + (i << 8)] = pk;
    }
}

// ---------------- V transpose [L][H] fp32 -> [H][L] bf16 ----------------
__global__ void transpose_bf16_kernel(const float* __restrict__ in,
                                      __nv_bfloat16* __restrict__ out) {
    __shared__ float tile[32][33];
    int j0 = blockIdx.x * 32, d0 = blockIdx.y * 32;
    int tx = threadIdx.x, ty = threadIdx.y;
#pragma unroll
    for (int i = 0; i < 4; i++) {
        int jj = ty + i * 8;
        tile[jj][tx] = in[(size_t)(j0 + jj) * H + d0 + tx];
    }
    __syncthreads();
#pragma unroll
    for (int i = 0; i < 4; i++) {
        int dd = ty + i * 8;
        out[(size_t)(d0 + dd) * L + j0 + tx] = __float2bfloat16_rn(tile[tx][dd]);
    }
}

// ---------------- combine split-K partials + residual ----------------
__global__ void combine_pv_kernel(const float* __restrict__ part, float* __restrict__ h) {
    int idx = blockIdx.x * 256 + threadIdx.x;
    float v = h[idx] + part[idx] + part[idx + LH] + part[idx + 2*LH] + part[idx + 3*LH];
    h[idx] = v;
}

// ---------------- launch ----------------
extern "C" void kernel_launch(void* const* d_in, const int* in_sizes, int n_in,
                              void* d_out, int out_size) {
    const float* x      = (const float*)d_in[0];
    const float* conv_w = (const float*)d_in[1];
    const float* conv_b = (const float*)d_in[2];
    const float* Wq     = (const float*)d_in[3];
    const float* bq     = (const float*)d_in[4];
    const float* Wk     = (const float*)d_in[5];
    const float* bk     = (const float*)d_in[6];
    const float* Wv     = (const float*)d_in[7];
    const float* bv     = (const float*)d_in[8];
    const float* Wff    = (const float*)d_in[9];
    const float* bff    = (const float*)d_in[10];
    float* out = (float*)d_out;

    float *p_h, *p_n, *p_v, *p_part, *p_wT, *p_S;
    __nv_bfloat16 *p_qb, *p_kb, *p_vtb, *p_P;
    cudaGetSymbolAddress((void**)&p_h,   g_h);
    cudaGetSymbolAddress((void**)&p_n,   g_n);
    cudaGetSymbolAddress((void**)&p_v,   g_v);
    cudaGetSymbolAddress((void**)&p_part,g_part);
    cudaGetSymbolAddress((void**)&p_wT,  g_wT);
    cudaGetSymbolAddress((void**)&p_S,   g_S);
    cudaGetSymbolAddress((void**)&p_qb,  g_qb);
    cudaGetSymbolAddress((void**)&p_kb,  g_kb);
    cudaGetSymbolAddress((void**)&p_vtb, g_vtb);
    cudaGetSymbolAddress((void**)&p_P,   g_P);

    static int s_attr_done = 0;
    if (!s_attr_done) {
        cudaFuncSetAttribute(gemm_bf16_tc, cudaFuncAttributeMaxDynamicSharedMemorySize, 2*STAGE_BYTES);
        s_attr_done = 1;
    }

    const float scale = 0.08838834764831845f;  // 1/sqrt(128)

    prep_w_kernel<<<1792, 256>>>(conv_w, p_wT);
    posenc_kernel<<<4096, 256>>>(x, p_h);

    for (int ic = 0; ic < NC; ic++) {
        ln_kernel<<<1024, 256>>>(p_h, p_n);
        conv_kernel<<<256, 256>>>(p_n, p_wT + (size_t)ic * KS * H * H,
                                  conv_b + ic * H, p_h);
    }

    // attention
    ln_kernel<<<1024, 256>>>(p_h, p_n);
    // q (pre-scaled by 1/sqrt(H), bf16), k (bf16), v (fp32)
    gemm_nt_kernel<<<dim3(2, 128), 256>>>(p_n, Wq, bq, nullptr, p_qb, L, H, H, scale, 0, 1);
    gemm_nt_kernel<<<dim3(2, 128), 256>>>(p_n, Wk, bk, nullptr, p_kb, L, H, H, 1.f, 0, 1);
    gemm_nt_kernel<<<dim3(2, 128), 256>>>(p_n, Wv, bv, nullptr, p_v,  L, H, H, 1.f, 0, 0);

    // S = q_scaled @ k^T  (bf16 tensor cores)
    gemm_bf16_tc<<<dim3(64, 64, 1), 256, 2*STAGE_BYTES>>>(p_qb, H, p_kb, H, p_S, L, H, 0);

    softmax_kernel<<<L, 256>>>(p_S, p_P);
    transpose_bf16_kernel<<<dim3(256, 4), dim3(32, 8)>>>(p_v, p_vtb);

    // PV = P @ V  via split-K x4 (bf16 tensor cores), partials fp32
    gemm_bf16_tc<<<dim3(1, 64, 4), 256, 2*STAGE_BYTES>>>(p_P, L, p_vtb, L, p_part, H, 2048, (size_t)LH);
    combine_pv_kernel<<<4096, 256>>>(p_part, p_h);

    // feed-forward
    ln_kernel<<<1024, 256>>>(p_h, p_n);
    gemm_nt_kernel<<<dim3(2, 128), 256>>>(p_n, Wff, bff, p_h, out, L, H, H, 1.f, 1, 0);
}

// round 3
// speedup vs baseline: 4.6393x; 1.6039x over previous
#include <cuda_runtime.h>
#include <cuda_bf16.h>
#include <math.h>
#include <stdint.h>

#define L 8192
#define H 128
#define NC 4
#define KS 7
#define LH (L*H)

// ---------------- scratch (static device memory) ----------------
__device__ float g_h [LH];
__device__ float g_n [LH];
__device__ float g_v [LH];
__device__ float g_part[4*LH];                 // split-K partials for PV
__device__ __nv_bfloat16 g_nh[LH];             // LN out hi (bf16)
__device__ __nv_bfloat16 g_nl[LH];             // LN out lo (bf16)
__device__ __nv_bfloat16 g_wh[NC*KS*H*H];      // conv W hi [ic][k][o][c]
__device__ __nv_bfloat16 g_wl[NC*KS*H*H];      // conv W lo
__device__ __nv_bfloat16 g_qb[LH];
__device__ __nv_bfloat16 g_kb[LH];
__device__ __nv_bfloat16 g_vtb[LH];            // V^T [H][L] bf16
__device__ __nv_bfloat16 g_S [(size_t)L*L];    // attention logits/probs bf16 (128MB)

// ================= helpers =================
__device__ __forceinline__ void cp16(uint32_t dst, const void* src) {
    asm volatile("cp.async.cg.shared.global [%0], [%1], 16;\n" :: "r"(dst), "l"(src));
}
__device__ __forceinline__ void ldsm4(uint32_t* r, uint32_t addr) {
    asm volatile("ldmatrix.sync.aligned.m8n8.x4.shared.b16 {%0,%1,%2,%3}, [%4];"
        : "=r"(r[0]), "=r"(r[1]), "=r"(r[2]), "=r"(r[3]) : "r"(addr));
}
__device__ __forceinline__ void mma16816(float* c, const uint32_t* a, uint32_t b0, uint32_t b1) {
    asm volatile("mma.sync.aligned.m16n8k16.row.col.f32.bf16.bf16.f32 "
        "{%0,%1,%2,%3}, {%4,%5,%6,%7}, {%8,%9}, {%0,%1,%2,%3};"
        : "+f"(c[0]), "+f"(c[1]), "+f"(c[2]), "+f"(c[3])
        : "r"(a[0]), "r"(a[1]), "r"(a[2]), "r"(a[3]), "r"(b0), "r"(b1));
}

// ---------------- positional encoding + add ----------------
__global__ void posenc_kernel(const float* __restrict__ x, float* __restrict__ h) {
    int idx = blockIdx.x * 256 + threadIdx.x;
    int l = idx >> 7, i = idx & 127;
    float di = (float)((i >> 1) << 1);
    float denom = powf(10000.0f, di * (1.0f / 128.0f));
    float ang = (float)l / denom;
    float pe = (i & 1) ? cosf(ang) : sinf(ang);
    h[idx] = x[idx] + pe;
}

// ---------------- layernorm (fp32 out) ----------------
__global__ void ln_kernel(const float* __restrict__ in, float* __restrict__ out) {
    int warp = threadIdx.x >> 5, lane = threadIdx.x & 31;
    int row = blockIdx.x * 8 + warp;
    const float4* ip = reinterpret_cast<const float4*>(in + (size_t)row * H);
    float4 v = ip[lane];
    float s = v.x + v.y + v.z + v.w;
    float q = v.x*v.x + v.y*v.y + v.z*v.z + v.w*v.w;
#pragma unroll
    for (int o = 16; o > 0; o >>= 1) {
        s += __shfl_xor_sync(0xffffffffu, s, o);
        q += __shfl_xor_sync(0xffffffffu, q, o);
    }
    float mu  = s * (1.0f / H);
    float var = q * (1.0f / H) - mu * mu;
    float inv = rsqrtf(var + 1e-5f);
    float4 o4 = make_float4((v.x-mu)*inv, (v.y-mu)*inv, (v.z-mu)*inv, (v.w-mu)*inv);
    reinterpret_cast<float4*>(out + (size_t)row * H)[lane] = o4;
}

// ---------------- layernorm with bf16 hi/lo split output ----------------
__global__ void ln_split_kernel(const float* __restrict__ in,
                                __nv_bfloat16* __restrict__ oh,
                                __nv_bfloat16* __restrict__ ol) {
    int warp = threadIdx.x >> 5, lane = threadIdx.x & 31;
    int row = blockIdx.x * 8 + warp;
    const float4* ip = reinterpret_cast<const float4*>(in + (size_t)row * H);
    float4 v = ip[lane];
    float s = v.x + v.y + v.z + v.w;
    float q = v.x*v.x + v.y*v.y + v.z*v.z + v.w*v.w;
#pragma unroll
    for (int o = 16; o > 0; o >>= 1) {
        s += __shfl_xor_sync(0xffffffffu, s, o);
        q += __shfl_xor_sync(0xffffffffu, q, o);
    }
    float mu  = s * (1.0f / H);
    float var = q * (1.0f / H) - mu * mu;
    float inv = rsqrtf(var + 1e-5f);
    float f[4] = {(v.x-mu)*inv, (v.y-mu)*inv, (v.z-mu)*inv, (v.w-mu)*inv};
    __nv_bfloat16 hi[4], lo[4];
#pragma unroll
    for (int i = 0; i < 4; i++) {
        hi[i] = __float2bfloat16_rn(f[i]);
        lo[i] = __float2bfloat16_rn(f[i] - __bfloat162float(hi[i]));
    }
    *reinterpret_cast<uint2*>(oh + (size_t)row * H + lane * 4) = *reinterpret_cast<uint2*>(hi);
    *reinterpret_cast<uint2*>(ol + (size_t)row * H + lane * 4) = *reinterpret_cast<uint2*>(lo);
}

// ---------------- conv weight prep: w[ic][o][c][k] -> hi/lo bf16 [ic][k][o][c] ----------------
__global__ void prep_w_kernel(const float* __restrict__ w,
                              __nv_bfloat16* __restrict__ wh,
                              __nv_bfloat16* __restrict__ wl) {
    int idx = blockIdx.x * 256 + threadIdx.x;      // NC*KS*H*H = 458752
    int c  = idx & 127;
    int o  = (idx >> 7) & 127;
    int t7 = idx >> 14;
    int k  = t7 % 7;
    int ic = t7 / 7;
    float v = w[(((size_t)ic * H + o) * H + c) * KS + k];
    __nv_bfloat16 hi = __float2bfloat16_rn(v);
    wh[idx] = hi;
    wl[idx] = __float2bfloat16_rn(v - __bfloat162float(hi));
}

// ---------------- conv1d SAME (K=7) via tensor cores, bf16x3 ----------------
// grid 128 blocks, each computes 64 rows x 128 out-channels.
// A smem: 4 regions [prec(2) x khalf(2)] of 72 rows x 64 bf16 (swizzled, 9216B each)
// B smem: 2 stage buffers of (hi 16KB + lo 16KB)
#define CONV_SMEM (36864 + 65536)
__global__ __launch_bounds__(256) void conv_tc_kernel(
    const __nv_bfloat16* __restrict__ nh, const __nv_bfloat16* __restrict__ nl,
    const __nv_bfloat16* __restrict__ wh, const __nv_bfloat16* __restrict__ wl,
    const float* __restrict__ bias, float* __restrict__ h)
{
    extern __shared__ __align__(128) char smem[];
    uint32_t sb = (uint32_t)__cvta_generic_to_shared(smem);
    uint32_t Abase = sb;
    uint32_t Bbase = sb + 36864;
    int t = threadIdx.x;
    int m0 = blockIdx.x << 6;

    // ---- load A: 4 regions x 72 rows x 8 chunks of 16B ----
    for (int i = t; i < 2304; i += 256) {
        int reg = i / 576;
        int rem = i - reg * 576;
        int r = rem >> 3, ch = rem & 7;
        int prec = reg >> 1, c64 = reg & 1;
        int gr = m0 - 3 + r;
        uint32_t off = reg * 9216 + r * 128 + ((ch ^ (r & 7)) << 4);
        if (gr >= 0 && gr < L) {
            const __nv_bfloat16* src = (prec ? nl : nh) + (size_t)gr * 128 + c64 * 64 + ch * 8;
            cp16(Abase + off, src);
        } else {
            *reinterpret_cast<uint4*>(smem + off) = make_uint4(0, 0, 0, 0);
        }
    }

    // ---- B stage loader ----
    auto load_B = [&](int s) {
        int k = s >> 1, c64 = s & 1, buf = s & 1;
#pragma unroll
        for (int i = 0; i < 8; i++) {
            int idx = t + (i << 8);          // 0..2047
            int prec = idx >> 10;
            int rem = idx & 1023;
            int o = rem >> 3, ch = rem & 7;
            const __nv_bfloat16* src = (prec ? wl : wh) + (size_t)(k * 128 + o) * 128 + c64 * 64 + ch * 8;
            uint32_t dst = Bbase + buf * 32768 + prec * 16384 + o * 128 + ((ch ^ (o & 7)) << 4);
            cp16(dst, src);
        }
    };

    int warp = t >> 5, lane = t & 31;
    int wm = warp >> 1, wn = warp & 1;

    float acc[8][4];
#pragma unroll
    for (int nt = 0; nt < 8; nt++)
#pragma unroll
        for (int i = 0; i < 4; i++) acc[nt][i] = 0.f;

    load_B(0);
    asm volatile("cp.async.commit_group;\n");

    int rowpat = (lane & 7) + (((lane >> 3) & 1) << 3);   // 0..15
    int chA_hi = (lane >> 4) & 1;
    int rowB = (lane & 7) + ((lane >> 4) << 3);
    int chB_hi = (lane >> 3) & 1;

    for (int s = 0; s < 14; s++) {
        if (s + 1 < 14) {
            load_B(s + 1);
            asm volatile("cp.async.commit_group;\n");
            asm volatile("cp.async.wait_group 1;\n");
        } else {
            asm volatile("cp.async.wait_group 0;\n");
        }
        __syncthreads();

        int k = s >> 1, c64 = s & 1;
        uint32_t Ahi = Abase + c64 * 9216;            // prec0 region
        uint32_t Alo = Ahi + 18432;                   // prec1 region (+2 regions)
        uint32_t Bh = Bbase + (s & 1) * 32768;
        uint32_t Bl = Bh + 16384;

#pragma unroll
        for (int k16 = 0; k16 < 4; k16++) {
            int ch = (k16 << 1) + chA_hi;
            int rA = (wm << 4) + rowpat + k;
            uint32_t aoff = rA * 128 + ((ch ^ (rA & 7)) << 4);
            uint32_t afr_h[4], afr_l[4];
            ldsm4(afr_h, Ahi + aoff);
            ldsm4(afr_l, Alo + aoff);

            int chb = (k16 << 1) + chB_hi;
            uint32_t bfr_h[4][4], bfr_l[4][4];
#pragma unroll
            for (int np = 0; np < 4; np++) {
                int rB = (wn << 6) + (np << 4) + rowB;
                uint32_t boff = rB * 128 + ((chb ^ (rB & 7)) << 4);
                ldsm4(bfr_h[np], Bh + boff);
                ldsm4(bfr_l[np], Bl + boff);
            }
#pragma unroll
            for (int nt = 0; nt < 8; nt++) {
                uint32_t b0h = bfr_h[nt >> 1][(nt & 1) << 1], b1h = bfr_h[nt >> 1][((nt & 1) << 1) + 1];
                uint32_t b0l = bfr_l[nt >> 1][(nt & 1) << 1], b1l = bfr_l[nt >> 1][((nt & 1) << 1) + 1];
                mma16816(acc[nt], afr_h, b0h, b1h);
                mma16816(acc[nt], afr_h, b0l, b1l);
                mma16816(acc[nt], afr_l, b0h, b1h);
            }
        }
        __syncthreads();
    }

    // ---- epilogue: + bias + residual h (in place) ----
    int g = lane >> 2, tq = lane & 3;
#pragma unroll
    for (int nt = 0; nt < 8; nt++) {
        int r = m0 + (wm << 4) + g;
        int cc = (wn << 6) + (nt << 3) + (tq << 1);
        float b0 = bias[cc], b1 = bias[cc + 1];
        float2 h0 = *reinterpret_cast<float2*>(h + (size_t)r * H + cc);
        float2 h1 = *reinterpret_cast<float2*>(h + (size_t)(r + 8) * H + cc);
        h0.x += acc[nt][0] + b0; h0.y += acc[nt][1] + b1;
        h1.x += acc[nt][2] + b0; h1.y += acc[nt][3] + b1;
        *reinterpret_cast<float2*>(h + (size_t)r * H + cc) = h0;
        *reinterpret_cast<float2*>(h + (size_t)(r + 8) * H + cc) = h1;
    }
}

// ---------------- fp32 NT GEMM (projections / FF) ----------------
__global__ __launch_bounds__(256) void gemm_nt_kernel(
    const float* __restrict__ A, const float* __restrict__ B,
    const float* __restrict__ bias, const float* __restrict__ resid,
    void* __restrict__ Cout, int M, int N, int K, float scale,
    int do_relu, int out_bf16)
{
    __shared__ float sA[64][33];
    __shared__ float sB[64][33];
    int t = threadIdx.x;
    int m0 = blockIdx.y << 6, n0 = blockIdx.x << 6;
    int warp = t >> 5, lane = t & 31;
    int ty = ((warp & 3) << 2) + (lane >> 3);
    int tx = ((warp >> 2) << 3) + (lane & 7);
    int row = ty << 2, col = tx << 2;

    float acc[4][4];
#pragma unroll
    for (int i = 0; i < 4; i++)
#pragma unroll
        for (int j = 0; j < 4; j++) acc[i][j] = 0.f;

    int lr = t >> 3;
    int lc = (t & 7) << 2;

    for (int k0 = 0; k0 < K; k0 += 32) {
#pragma unroll
        for (int it = 0; it < 2; it++) {
            int r = lr + it * 32;
            float4 va = *reinterpret_cast<const float4*>(A + (size_t)(m0 + r) * K + k0 + lc);
            sA[r][lc+0] = va.x; sA[r][lc+1] = va.y; sA[r][lc+2] = va.z; sA[r][lc+3] = va.w;
            float4 vb = *reinterpret_cast<const float4*>(B + (size_t)(n0 + r) * K + k0 + lc);
            sB[r][lc+0] = vb.x; sB[r][lc+1] = vb.y; sB[r][lc+2] = vb.z; sB[r][lc+3] = vb.w;
        }
        __syncthreads();
#pragma unroll 8
        for (int kk = 0; kk < 32; kk++) {
            float a0 = sA[row+0][kk], a1 = sA[row+1][kk], a2 = sA[row+2][kk], a3 = sA[row+3][kk];
            float b0 = sB[col+0][kk], b1 = sB[col+1][kk], b2 = sB[col+2][kk], b3 = sB[col+3][kk];
            acc[0][0] = fmaf(a0,b0,acc[0][0]); acc[0][1] = fmaf(a0,b1,acc[0][1]);
            acc[0][2] = fmaf(a0,b2,acc[0][2]); acc[0][3] = fmaf(a0,b3,acc[0][3]);
            acc[1][0] = fmaf(a1,b0,acc[1][0]); acc[1][1] = fmaf(a1,b1,acc[1][1]);
            acc[1][2] = fmaf(a1,b2,acc[1][2]); acc[1][3] = fmaf(a1,b3,acc[1][3]);
            acc[2][0] = fmaf(a2,b0,acc[2][0]); acc[2][1] = fmaf(a2,b1,acc[2][1]);
            acc[2][2] = fmaf(a2,b2,acc[2][2]); acc[2][3] = fmaf(a2,b3,acc[2][3]);
            acc[3][0] = fmaf(a3,b0,acc[3][0]); acc[3][1] = fmaf(a3,b1,acc[3][1]);
            acc[3][2] = fmaf(a3,b2,acc[3][2]); acc[3][3] = fmaf(a3,b3,acc[3][3]);
        }
        __syncthreads();
    }

    float bv[4] = {0.f, 0.f, 0.f, 0.f};
    if (bias) {
        bv[0] = bias[n0+col+0]; bv[1] = bias[n0+col+1];
        bv[2] = bias[n0+col+2]; bv[3] = bias[n0+col+3];
    }
#pragma unroll
    for (int i = 0; i < 4; i++) {
        size_t ci = (size_t)(m0 + row + i) * N + n0 + col;
        float4 r4 = make_float4(0.f, 0.f, 0.f, 0.f);
        if (resid) r4 = *reinterpret_cast<const float4*>(resid + ci);
        float v0 = (acc[i][0] + bv[0]) * scale;
        float v1 = (acc[i][1] + bv[1]) * scale;
        float v2 = (acc[i][2] + bv[2]) * scale;
        float v3 = (acc[i][3] + bv[3]) * scale;
        if (do_relu) {
            v0 = fmaxf(v0, 0.f); v1 = fmaxf(v1, 0.f);
            v2 = fmaxf(v2, 0.f); v3 = fmaxf(v3, 0.f);
        }
        v0 += r4.x; v1 += r4.y; v2 += r4.z; v3 += r4.w;
        if (out_bf16) {
            __nv_bfloat162 p0 = __floats2bfloat162_rn(v0, v1);
            __nv_bfloat162 p1 = __floats2bfloat162_rn(v2, v3);
            uint2 pk; pk.x = *reinterpret_cast<uint32_t*>(&p0); pk.y = *reinterpret_cast<uint32_t*>(&p1);
            *reinterpret_cast<uint2*>((__nv_bfloat16*)Cout + ci) = pk;
        } else {
            *reinterpret_cast<float4*>((float*)Cout + ci) = make_float4(v0, v1, v2, v3);
        }
    }
}

// ---------------- bf16 tensor-core NT GEMM (S and PV) ----------------
#define STAGE_BYTES 32768   // 16KB A + 16KB B

__device__ __forceinline__ void load_stage_tc(
    const __nv_bfloat16* At, int ldA, const __nv_bfloat16* Bt, int ldB,
    uint32_t sbase, int t)
{
#pragma unroll
    for (int i = 0; i < 4; i++) {
        int idx = t + (i << 8);
        int row = idx >> 3, ch = idx & 7;
        uint32_t dst = sbase + row * 128 + ((ch ^ (row & 7)) << 4);
        cp16(dst, At + (size_t)row * ldA + (ch << 3));
    }
#pragma unroll
    for (int i = 0; i < 4; i++) {
        int idx = t + (i << 8);
        int row = idx >> 3, ch = idx & 7;
        uint32_t dst = sbase + 16384 + row * 128 + ((ch ^ (row & 7)) << 4);
        cp16(dst, Bt + (size_t)row * ldB + (ch << 3));
    }
}

__global__ __launch_bounds__(256) void gemm_bf16_tc(
    const __nv_bfloat16* __restrict__ A, int ldA,
    const __nv_bfloat16* __restrict__ B, int ldB,
    void* __restrict__ Cv, int ldC, int Klen, size_t cSliceStride, int out_bf16)
{
    extern __shared__ __align__(128) char smem[];
    uint32_t sbase = (uint32_t)__cvta_generic_to_shared(smem);
    int t = threadIdx.x;
    int m0 = blockIdx.y << 7, n0 = blockIdx.x << 7;
    size_t koff = (size_t)blockIdx.z * Klen;
    A += (size_t)m0 * ldA + koff;
    B += (size_t)n0 * ldB + koff;

    int warp = t >> 5, lane = t & 31;
    int wm = warp >> 1, wn = warp & 1;

    float acc[2][8][4];
#pragma unroll
    for (int mt = 0; mt < 2; mt++)
#pragma unroll
        for (int nt = 0; nt < 8; nt++)
#pragma unroll
            for (int i = 0; i < 4; i++) acc[mt][nt][i] = 0.f;

    int nCh = Klen >> 6;
    load_stage_tc(A, ldA, B, ldB, sbase, t);
    asm volatile("cp.async.commit_group;\n");

    for (int c = 0; c < nCh; c++) {
        if (c + 1 < nCh) {
            load_stage_tc(A + ((c + 1) << 6), ldA, B + ((c + 1) << 6), ldB,
                          sbase + ((c + 1) & 1) * STAGE_BYTES, t);
            asm volatile("cp.async.commit_group;\n");
            asm volatile("cp.async.wait_group 1;\n");
        } else {
            asm volatile("cp.async.wait_group 0;\n");
        }
        __syncthreads();

        uint32_t aB = sbase + (c & 1) * STAGE_BYTES;
        uint32_t bB = aB + 16384;
#pragma unroll
        for (int k16 = 0; k16 < 4; k16++) {
            uint32_t afr[2][4];
#pragma unroll
            for (int mt = 0; mt < 2; mt++) {
                int row = (wm << 5) + (mt << 4) + (lane & 7) + (((lane >> 3) & 1) << 3);
                int ch  = (k16 << 1) + ((lane >> 4) & 1);
                ldsm4(afr[mt], aB + row * 128 + ((ch ^ (row & 7)) << 4));
            }
            uint32_t bfr[4][4];
#pragma unroll
            for (int np = 0; np < 4; np++) {
                int row = (wn << 6) + (np << 4) + (lane & 7) + ((lane >> 4) << 3);
                int ch  = (k16 << 1) + ((lane >> 3) & 1);
                ldsm4(bfr[np], bB + row * 128 + ((ch ^ (row & 7)) << 4));
            }
#pragma unroll
            for (int mt = 0; mt < 2; mt++)
#pragma unroll
                for (int nt = 0; nt < 8; nt++)
                    mma16816(acc[mt][nt], afr[mt],
                             bfr[nt >> 1][(nt & 1) << 1], bfr[nt >> 1][((nt & 1) << 1) + 1]);
        }
        __syncthreads();
    }

    // epilogue
    int g = lane >> 2, tq = lane & 3;
#pragma unroll
    for (int mt = 0; mt < 2; mt++) {
#pragma unroll
        for (int nt = 0; nt < 8; nt++) {
            int r = m0 + (wm << 5) + (mt << 4) + g;
            int cc = n0 + (wn << 6) + (nt << 3) + (tq << 1);
            if (out_bf16) {
                __nv_bfloat16* Cb = (__nv_bfloat16*)Cv;
                __nv_bfloat162 p0 = __floats2bfloat162_rn(acc[mt][nt][0], acc[mt][nt][1]);
                __nv_bfloat162 p1 = __floats2bfloat162_rn(acc[mt][nt][2], acc[mt][nt][3]);
                *reinterpret_cast<uint32_t*>(Cb + (size_t)r * ldC + cc) = *reinterpret_cast<uint32_t*>(&p0);
                *reinterpret_cast<uint32_t*>(Cb + (size_t)(r + 8) * ldC + cc) = *reinterpret_cast<uint32_t*>(&p1);
            } else {
                float* C = (float*)Cv + (size_t)blockIdx.z * cSliceStride;
                *reinterpret_cast<float2*>(C + (size_t)r * ldC + cc) = make_float2(acc[mt][nt][0], acc[mt][nt][1]);
                *reinterpret_cast<float2*>(C + (size_t)(r + 8) * ldC + cc) = make_float2(acc[mt][nt][2], acc[mt][nt][3]);
            }
        }
    }
}

// ---------------- row softmax bf16 in-place ----------------
__global__ __launch_bounds__(256) void softmax_bf16_kernel(__nv_bfloat16* __restrict__ S) {
    __shared__ float red[8];
    int t = threadIdx.x;
    int warp = t >> 5, lane = t & 31;
    uint4* rp = reinterpret_cast<uint4*>(S + (size_t)blockIdx.x * L);
    float f[32];
    uint4 raw[4];
    float mx = -3.4e38f;
#pragma unroll
    for (int i = 0; i < 4; i++) {
        raw[i] = rp[t + (i << 8)];
        const uint32_t* w = reinterpret_cast<const uint32_t*>(&raw[i]);
#pragma unroll
        for (int j = 0; j < 4; j++) {
            float2 p = __bfloat1622float2(*reinterpret_cast<const __nv_bfloat162*>(&w[j]));
            f[i*8 + j*2]     = p.x;
            f[i*8 + j*2 + 1] = p.y;
            mx = fmaxf(mx, fmaxf(p.x, p.y));
        }
    }
#pragma unroll
    for (int o = 16; o > 0; o >>= 1) mx = fmaxf(mx, __shfl_xor_sync(0xffffffffu, mx, o));
    if (lane == 0) red[warp] = mx;
    __syncthreads();
    mx = red[0];
#pragma unroll
    for (int i = 1; i < 8; i++) mx = fmaxf(mx, red[i]);
    __syncthreads();

    float sum = 0.f;
#pragma unroll
    for (int i = 0; i < 32; i++) {
        f[i] = expf(f[i] - mx);
        sum += f[i];
    }
#pragma unroll
    for (int o = 16; o > 0; o >>= 1) sum += __shfl_xor_sync(0xffffffffu, sum, o);
    if (lane == 0) red[warp] = sum;
    __syncthreads();
    sum = 0.f;
#pragma unroll
    for (int i = 0; i < 8; i++) sum += red[i];
    float inv = 1.0f / sum;
#pragma unroll
    for (int i = 0; i < 4; i++) {
        uint4 outv;
        uint32_t* w = reinterpret_cast<uint32_t*>(&outv);
#pragma unroll
        for (int j = 0; j < 4; j++) {
            __nv_bfloat162 p = __floats2bfloat162_rn(f[i*8 + j*2] * inv, f[i*8 + j*2 + 1] * inv);
            w[j] = *reinterpret_cast<uint32_t*>(&p);
        }
        rp[t + (i << 8)] = outv;
    }
}

// ---------------- V transpose [L][H] fp32 -> [H][L] bf16 ----------------
__global__ void transpose_bf16_kernel(const float* __restrict__ in,
                                      __nv_bfloat16* __restrict__ out) {
    __shared__ float tile[32][33];
    int j0 = blockIdx.x * 32, d0 = blockIdx.y * 32;
    int tx = threadIdx.x, ty = threadIdx.y;
#pragma unroll
    for (int i = 0; i < 4; i++) {
        int jj = ty + i * 8;
        tile[jj][tx] = in[(size_t)(j0 + jj) * H + d0 + tx];
    }
    __syncthreads();
#pragma unroll
    for (int i = 0; i < 4; i++) {
        int dd = ty + i * 8;
        out[(size_t)(d0 + dd) * L + j0 + tx] = __float2bfloat16_rn(tile[tx][dd]);
    }
}

// ---------------- combine split-K partials + residual ----------------
__global__ void combine_pv_kernel(const float* __restrict__ part, float* __restrict__ h) {
    int idx = blockIdx.x * 256 + threadIdx.x;
    float v = h[idx] + part[idx] + part[idx + LH] + part[idx + 2*LH] + part[idx + 3*LH];
    h[idx] = v;
}

// ---------------- launch ----------------
extern "C" void kernel_launch(void* const* d_in, const int* in_sizes, int n_in,
                              void* d_out, int out_size) {
    const float* x      = (const float*)d_in[0];
    const float* conv_w = (const float*)d_in[1];
    const float* conv_b = (const float*)d_in[2];
    const float* Wq     = (const float*)d_in[3];
    const float* bq     = (const float*)d_in[4];
    const float* Wk     = (const float*)d_in[5];
    const float* bk     = (const float*)d_in[6];
    const float* Wv     = (const float*)d_in[7];
    const float* bv     = (const float*)d_in[8];
    const float* Wff    = (const float*)d_in[9];
    const float* bff    = (const float*)d_in[10];
    float* out = (float*)d_out;

    float *p_h, *p_n, *p_v, *p_part;
    __nv_bfloat16 *p_nh, *p_nl, *p_wh, *p_wl, *p_qb, *p_kb, *p_vtb, *p_S;
    cudaGetSymbolAddress((void**)&p_h,   g_h);
    cudaGetSymbolAddress((void**)&p_n,   g_n);
    cudaGetSymbolAddress((void**)&p_v,   g_v);
    cudaGetSymbolAddress((void**)&p_part,g_part);
    cudaGetSymbolAddress((void**)&p_nh,  g_nh);
    cudaGetSymbolAddress((void**)&p_nl,  g_nl);
    cudaGetSymbolAddress((void**)&p_wh,  g_wh);
    cudaGetSymbolAddress((void**)&p_wl,  g_wl);
    cudaGetSymbolAddress((void**)&p_qb,  g_qb);
    cudaGetSymbolAddress((void**)&p_kb,  g_kb);
    cudaGetSymbolAddress((void**)&p_vtb, g_vtb);
    cudaGetSymbolAddress((void**)&p_S,   g_S);

    static int s_attr_done = 0;
    if (!s_attr_done) {
        cudaFuncSetAttribute(gemm_bf16_tc, cudaFuncAttributeMaxDynamicSharedMemorySize, 2*STAGE_BYTES);
        cudaFuncSetAttribute(conv_tc_kernel, cudaFuncAttributeMaxDynamicSharedMemorySize, CONV_SMEM);
        s_attr_done = 1;
    }

    const float scale = 0.08838834764831845f;  // 1/sqrt(128)

    prep_w_kernel<<<1792, 256>>>(conv_w, p_wh, p_wl);
    posenc_kernel<<<4096, 256>>>(x, p_h);

    for (int ic = 0; ic < NC; ic++) {
        ln_split_kernel<<<1024, 256>>>(p_h, p_nh, p_nl);
        conv_tc_kernel<<<128, 256, CONV_SMEM>>>(p_nh, p_nl,
                                                p_wh + (size_t)ic * KS * H * H,
                                                p_wl + (size_t)ic * KS * H * H,
                                                conv_b + ic * H, p_h);
    }

    // attention
    ln_kernel<<<1024, 256>>>(p_h, p_n);
    gemm_nt_kernel<<<dim3(2, 128), 256>>>(p_n, Wq, bq, nullptr, p_qb, L, H, H, scale, 0, 1);
    gemm_nt_kernel<<<dim3(2, 128), 256>>>(p_n, Wk, bk, nullptr, p_kb, L, H, H, 1.f, 0, 1);
    gemm_nt_kernel<<<dim3(2, 128), 256>>>(p_n, Wv, bv, nullptr, p_v,  L, H, H, 1.f, 0, 0);

    // S = q_scaled @ k^T  (bf16 out)
    gemm_bf16_tc<<<dim3(64, 64, 1), 256, 2*STAGE_BYTES>>>(p_qb, H, p_kb, H, p_S, L, H, 0, 1);
    softmax_bf16_kernel<<<L, 256>>>(p_S);
    transpose_bf16_kernel<<<dim3(256, 4), dim3(32, 8)>>>(p_v, p_vtb);

    // PV = P @ V via split-K x4, fp32 partials
    gemm_bf16_tc<<<dim3(1, 64, 4), 256, 2*STAGE_BYTES>>>(p_S, L, p_vtb, L, p_part, H, 2048, (size_t)LH, 0);
    combine_pv_kernel<<<4096, 256>>>(p_part, p_h);

    // feed-forward
    ln_kernel<<<1024, 256>>>(p_h, p_n);
    gemm_nt_kernel<<<dim3(2, 128), 256>>>(p_n, Wff, bff, p_h, out, L, H, H, 1.f, 1, 0);
}

// round 4
// speedup vs baseline: 5.9255x; 1.2772x over previous
#include <cuda_runtime.h>
#include <cuda_bf16.h>
#include <math.h>
#include <stdint.h>

#define L 8192
#define H 128
#define NC 4
#define KS 7
#define LH (L*H)

// ---------------- scratch (static device memory) ----------------
__device__ float g_h [LH];
__device__ float g_n [LH];
__device__ float g_v [LH];
__device__ float g_Opart[2*LH];                // flash O partials (2 KV splits)
__device__ float g_lp[2*L];                    // flash l partials
__device__ __nv_bfloat16 g_nh[LH];             // LN out hi (bf16)
__device__ __nv_bfloat16 g_nl[LH];             // LN out lo (bf16)
__device__ __nv_bfloat16 g_wh[NC*KS*H*H];      // conv W hi [ic][k][o][c]
__device__ __nv_bfloat16 g_wl[NC*KS*H*H];      // conv W lo
__device__ __nv_bfloat16 g_qb[LH];
__device__ __nv_bfloat16 g_kb[LH];
__device__ __nv_bfloat16 g_vtb[LH];            // V^T [H][L] bf16

// ================= helpers =================
__device__ __forceinline__ void cp16(uint32_t dst, const void* src) {
    asm volatile("cp.async.cg.shared.global [%0], [%1], 16;\n" :: "r"(dst), "l"(src));
}
__device__ __forceinline__ void ldsm4(uint32_t* r, uint32_t addr) {
    asm volatile("ldmatrix.sync.aligned.m8n8.x4.shared.b16 {%0,%1,%2,%3}, [%4];"
        : "=r"(r[0]), "=r"(r[1]), "=r"(r[2]), "=r"(r[3]) : "r"(addr));
}
__device__ __forceinline__ void mma16816(float* c, const uint32_t* a, uint32_t b0, uint32_t b1) {
    asm volatile("mma.sync.aligned.m16n8k16.row.col.f32.bf16.bf16.f32 "
        "{%0,%1,%2,%3}, {%4,%5,%6,%7}, {%8,%9}, {%0,%1,%2,%3};"
        : "+f"(c[0]), "+f"(c[1]), "+f"(c[2]), "+f"(c[3])
        : "r"(a[0]), "r"(a[1]), "r"(a[2]), "r"(a[3]), "r"(b0), "r"(b1));
}
__device__ __forceinline__ uint32_t packbf(float a, float b) {
    __nv_bfloat162 p = __floats2bfloat162_rn(a, b);
    return *reinterpret_cast<uint32_t*>(&p);
}

// ---------------- positional encoding + add ----------------
__global__ void posenc_kernel(const float* __restrict__ x, float* __restrict__ h) {
    int idx = blockIdx.x * 256 + threadIdx.x;
    int l = idx >> 7, i = idx & 127;
    float di = (float)((i >> 1) << 1);
    float denom = powf(10000.0f, di * (1.0f / 128.0f));
    float ang = (float)l / denom;
    float pe = (i & 1) ? cosf(ang) : sinf(ang);
    h[idx] = x[idx] + pe;
}

// ---------------- layernorm (fp32 out) ----------------
__global__ void ln_kernel(const float* __restrict__ in, float* __restrict__ out) {
    int warp = threadIdx.x >> 5, lane = threadIdx.x & 31;
    int row = blockIdx.x * 8 + warp;
    const float4* ip = reinterpret_cast<const float4*>(in + (size_t)row * H);
    float4 v = ip[lane];
    float s = v.x + v.y + v.z + v.w;
    float q = v.x*v.x + v.y*v.y + v.z*v.z + v.w*v.w;
#pragma unroll
    for (int o = 16; o > 0; o >>= 1) {
        s += __shfl_xor_sync(0xffffffffu, s, o);
        q += __shfl_xor_sync(0xffffffffu, q, o);
    }
    float mu  = s * (1.0f / H);
    float var = q * (1.0f / H) - mu * mu;
    float inv = rsqrtf(var + 1e-5f);
    float4 o4 = make_float4((v.x-mu)*inv, (v.y-mu)*inv, (v.z-mu)*inv, (v.w-mu)*inv);
    reinterpret_cast<float4*>(out + (size_t)row * H)[lane] = o4;
}

// ---------------- layernorm with bf16 hi/lo split output ----------------
__global__ void ln_split_kernel(const float* __restrict__ in,
                                __nv_bfloat16* __restrict__ oh,
                                __nv_bfloat16* __restrict__ ol) {
    int warp = threadIdx.x >> 5, lane = threadIdx.x & 31;
    int row = blockIdx.x * 8 + warp;
    const float4* ip = reinterpret_cast<const float4*>(in + (size_t)row * H);
    float4 v = ip[lane];
    float s = v.x + v.y + v.z + v.w;
    float q = v.x*v.x + v.y*v.y + v.z*v.z + v.w*v.w;
#pragma unroll
    for (int o = 16; o > 0; o >>= 1) {
        s += __shfl_xor_sync(0xffffffffu, s, o);
        q += __shfl_xor_sync(0xffffffffu, q, o);
    }
    float mu  = s * (1.0f / H);
    float var = q * (1.0f / H) - mu * mu;
    float inv = rsqrtf(var + 1e-5f);
    float f[4] = {(v.x-mu)*inv, (v.y-mu)*inv, (v.z-mu)*inv, (v.w-mu)*inv};
    __nv_bfloat16 hi[4], lo[4];
#pragma unroll
    for (int i = 0; i < 4; i++) {
        hi[i] = __float2bfloat16_rn(f[i]);
        lo[i] = __float2bfloat16_rn(f[i] - __bfloat162float(hi[i]));
    }
    *reinterpret_cast<uint2*>(oh + (size_t)row * H + lane * 4) = *reinterpret_cast<uint2*>(hi);
    *reinterpret_cast<uint2*>(ol + (size_t)row * H + lane * 4) = *reinterpret_cast<uint2*>(lo);
}

// ---------------- conv weight prep ----------------
__global__ void prep_w_kernel(const float* __restrict__ w,
                              __nv_bfloat16* __restrict__ wh,
                              __nv_bfloat16* __restrict__ wl) {
    int idx = blockIdx.x * 256 + threadIdx.x;
    int c  = idx & 127;
    int o  = (idx >> 7) & 127;
    int t7 = idx >> 14;
    int k  = t7 % 7;
    int ic = t7 / 7;
    float v = w[(((size_t)ic * H + o) * H + c) * KS + k];
    __nv_bfloat16 hi = __float2bfloat16_rn(v);
    wh[idx] = hi;
    wl[idx] = __float2bfloat16_rn(v - __bfloat162float(hi));
}

// ---------------- conv1d SAME (K=7) via tensor cores, bf16x3, 32 rows/block ----------------
// A smem: 4 regions [prec x c64] of 38 rows x 128B = 19456B ; B: 2 x 32768 = 65536
#define CONV_SMEM (19456 + 65536)
__global__ __launch_bounds__(256) void conv_tc_kernel(
    const __nv_bfloat16* __restrict__ nh, const __nv_bfloat16* __restrict__ nl,
    const __nv_bfloat16* __restrict__ wh, const __nv_bfloat16* __restrict__ wl,
    const float* __restrict__ bias, float* __restrict__ h)
{
    extern __shared__ __align__(128) char smem[];
    uint32_t sb = (uint32_t)__cvta_generic_to_shared(smem);
    uint32_t Abase = sb;
    uint32_t Bbase = sb + 19456;
    int t = threadIdx.x;
    int m0 = blockIdx.x << 5;

    // ---- load A: 4 regions x 38 rows x 8 chunks ----
    for (int i = t; i < 1216; i += 256) {
        int reg = i / 304;
        int rem = i - reg * 304;
        int r = rem >> 3, ch = rem & 7;
        int prec = reg >> 1, c64 = reg & 1;
        int gr = m0 - 3 + r;
        uint32_t off = reg * 4864 + r * 128 + ((ch ^ (r & 7)) << 4);
        if (gr >= 0 && gr < L) {
            const __nv_bfloat16* src = (prec ? nl : nh) + (size_t)gr * 128 + c64 * 64 + ch * 8;
            cp16(Abase + off, src);
        } else {
            *reinterpret_cast<uint4*>(smem + off) = make_uint4(0, 0, 0, 0);
        }
    }

    auto load_B = [&](int s) {
        int k = s >> 1, c64 = s & 1, buf = s & 1;
#pragma unroll
        for (int i = 0; i < 8; i++) {
            int idx = t + (i << 8);
            int prec = idx >> 10;
            int rem = idx & 1023;
            int o = rem >> 3, ch = rem & 7;
            const __nv_bfloat16* src = (prec ? wl : wh) + (size_t)(k * 128 + o) * 128 + c64 * 64 + ch * 8;
            uint32_t dst = Bbase + buf * 32768 + prec * 16384 + o * 128 + ((ch ^ (o & 7)) << 4);
            cp16(dst, src);
        }
    };

    int warp = t >> 5, lane = t & 31;
    int wm = warp >> 2, wn = warp & 3;

    float acc[4][4];
#pragma unroll
    for (int nt = 0; nt < 4; nt++)
#pragma unroll
        for (int i = 0; i < 4; i++) acc[nt][i] = 0.f;

    load_B(0);
    asm volatile("cp.async.commit_group;\n");

    int rowpat = (lane & 7) + (((lane >> 3) & 1) << 3);
    int chA_hi = (lane >> 4) & 1;
    int rowB = (lane & 7) + ((lane >> 4) << 3);
    int chB_hi = (lane >> 3) & 1;

    for (int s = 0; s < 14; s++) {
        if (s + 1 < 14) {
            load_B(s + 1);
            asm volatile("cp.async.commit_group;\n");
            asm volatile("cp.async.wait_group 1;\n");
        } else {
            asm volatile("cp.async.wait_group 0;\n");
        }
        __syncthreads();

        int k = s >> 1, c64 = s & 1;
        uint32_t Ahi = Abase + c64 * 4864;
        uint32_t Alo = Ahi + 9728;
        uint32_t Bh = Bbase + (s & 1) * 32768;
        uint32_t Bl = Bh + 16384;

#pragma unroll
        for (int k16 = 0; k16 < 4; k16++) {
            int ch = (k16 << 1) + chA_hi;
            int rA = (wm << 4) + rowpat + k;
            uint32_t aoff = rA * 128 + ((ch ^ (rA & 7)) << 4);
            uint32_t afr_h[4], afr_l[4];
            ldsm4(afr_h, Ahi + aoff);
            ldsm4(afr_l, Alo + aoff);

            int chb = (k16 << 1) + chB_hi;
            uint32_t bfr_h[2][4], bfr_l[2][4];
#pragma unroll
            for (int np = 0; np < 2; np++) {
                int rB = (wn << 5) + (np << 4) + rowB;
                uint32_t boff = rB * 128 + ((chb ^ (rB & 7)) << 4);
                ldsm4(bfr_h[np], Bh + boff);
                ldsm4(bfr_l[np], Bl + boff);
            }
#pragma unroll
            for (int nt = 0; nt < 4; nt++) {
                uint32_t b0h = bfr_h[nt >> 1][(nt & 1) << 1], b1h = bfr_h[nt >> 1][((nt & 1) << 1) + 1];
                uint32_t b0l = bfr_l[nt >> 1][(nt & 1) << 1], b1l = bfr_l[nt >> 1][((nt & 1) << 1) + 1];
                mma16816(acc[nt], afr_h, b0h, b1h);
                mma16816(acc[nt], afr_h, b0l, b1l);
                mma16816(acc[nt], afr_l, b0h, b1h);
            }
        }
        __syncthreads();
    }

    int g = lane >> 2, tq = lane & 3;
#pragma unroll
    for (int nt = 0; nt < 4; nt++) {
        int r = m0 + (wm << 4) + g;
        int cc = (wn << 5) + (nt << 3) + (tq << 1);
        float b0 = bias[cc], b1 = bias[cc + 1];
        float2 h0 = *reinterpret_cast<float2*>(h + (size_t)r * H + cc);
        float2 h1 = *reinterpret_cast<float2*>(h + (size_t)(r + 8) * H + cc);
        h0.x += acc[nt][0] + b0; h0.y += acc[nt][1] + b1;
        h1.x += acc[nt][2] + b0; h1.y += acc[nt][3] + b1;
        *reinterpret_cast<float2*>(h + (size_t)r * H + cc) = h0;
        *reinterpret_cast<float2*>(h + (size_t)(r + 8) * H + cc) = h1;
    }
}

// ---------------- fp32 NT GEMM (projections / FF) ----------------
__global__ __launch_bounds__(256) void gemm_nt_kernel(
    const float* __restrict__ A, const float* __restrict__ B,
    const float* __restrict__ bias, const float* __restrict__ resid,
    void* __restrict__ Cout, int M, int N, int K, float scale,
    int do_relu, int out_bf16)
{
    __shared__ float sA[64][33];
    __shared__ float sB[64][33];
    int t = threadIdx.x;
    int m0 = blockIdx.y << 6, n0 = blockIdx.x << 6;
    int warp = t >> 5, lane = t & 31;
    int ty = ((warp & 3) << 2) + (lane >> 3);
    int tx = ((warp >> 2) << 3) + (lane & 7);
    int row = ty << 2, col = tx << 2;

    float acc[4][4];
#pragma unroll
    for (int i = 0; i < 4; i++)
#pragma unroll
        for (int j = 0; j < 4; j++) acc[i][j] = 0.f;

    int lr = t >> 3;
    int lc = (t & 7) << 2;

    for (int k0 = 0; k0 < K; k0 += 32) {
#pragma unroll
        for (int it = 0; it < 2; it++) {
            int r = lr + it * 32;
            float4 va = *reinterpret_cast<const float4*>(A + (size_t)(m0 + r) * K + k0 + lc);
            sA[r][lc+0] = va.x; sA[r][lc+1] = va.y; sA[r][lc+2] = va.z; sA[r][lc+3] = va.w;
            float4 vb = *reinterpret_cast<const float4*>(B + (size_t)(n0 + r) * K + k0 + lc);
            sB[r][lc+0] = vb.x; sB[r][lc+1] = vb.y; sB[r][lc+2] = vb.z; sB[r][lc+3] = vb.w;
        }
        __syncthreads();
#pragma unroll 8
        for (int kk = 0; kk < 32; kk++) {
            float a0 = sA[row+0][kk], a1 = sA[row+1][kk], a2 = sA[row+2][kk], a3 = sA[row+3][kk];
            float b0 = sB[col+0][kk], b1 = sB[col+1][kk], b2 = sB[col+2][kk], b3 = sB[col+3][kk];
            acc[0][0] = fmaf(a0,b0,acc[0][0]); acc[0][1] = fmaf(a0,b1,acc[0][1]);
            acc[0][2] = fmaf(a0,b2,acc[0][2]); acc[0][3] = fmaf(a0,b3,acc[0][3]);
            acc[1][0] = fmaf(a1,b0,acc[1][0]); acc[1][1] = fmaf(a1,b1,acc[1][1]);
            acc[1][2] = fmaf(a1,b2,acc[1][2]); acc[1][3] = fmaf(a1,b3,acc[1][3]);
            acc[2][0] = fmaf(a2,b0,acc[2][0]); acc[2][1] = fmaf(a2,b1,acc[2][1]);
            acc[2][2] = fmaf(a2,b2,acc[2][2]); acc[2][3] = fmaf(a2,b3,acc[2][3]);
            acc[3][0] = fmaf(a3,b0,acc[3][0]); acc[3][1] = fmaf(a3,b1,acc[3][1]);
            acc[3][2] = fmaf(a3,b2,acc[3][2]); acc[3][3] = fmaf(a3,b3,acc[3][3]);
        }
        __syncthreads();
    }

    float bv[4] = {0.f, 0.f, 0.f, 0.f};
    if (bias) {
        bv[0] = bias[n0+col+0]; bv[1] = bias[n0+col+1];
        bv[2] = bias[n0+col+2]; bv[3] = bias[n0+col+3];
    }
#pragma unroll
    for (int i = 0; i < 4; i++) {
        size_t ci = (size_t)(m0 + row + i) * N + n0 + col;
        float4 r4 = make_float4(0.f, 0.f, 0.f, 0.f);
        if (resid) r4 = *reinterpret_cast<const float4*>(resid + ci);
        float v0 = (acc[i][0] + bv[0]) * scale;
        float v1 = (acc[i][1] + bv[1]) * scale;
        float v2 = (acc[i][2] + bv[2]) * scale;
        float v3 = (acc[i][3] + bv[3]) * scale;
        if (do_relu) {
            v0 = fmaxf(v0, 0.f); v1 = fmaxf(v1, 0.f);
            v2 = fmaxf(v2, 0.f); v3 = fmaxf(v3, 0.f);
        }
        v0 += r4.x; v1 += r4.y; v2 += r4.z; v3 += r4.w;
        if (out_bf16) {
            uint2 pk; pk.x = packbf(v0, v1); pk.y = packbf(v2, v3);
            *reinterpret_cast<uint2*>((__nv_bfloat16*)Cout + ci) = pk;
        } else {
            *reinterpret_cast<float4*>((float*)Cout + ci) = make_float4(v0, v1, v2, v3);
        }
    }
}

// ---------------- fused flash attention (no max-shift; logits are small) ----------------
// grid (2 kv-splits, 64 q-tiles), 256 threads = 8 warps x 16 Q rows.
// smem: Q 32KB + K 2x32KB + V 2x32KB = 160KB
#define FA_SMEM (32768 + 65536 + 65536)
__global__ __launch_bounds__(256, 1) void flash_kernel(
    const __nv_bfloat16* __restrict__ qb,
    const __nv_bfloat16* __restrict__ kb,
    const __nv_bfloat16* __restrict__ vt,
    float* __restrict__ Opart, float* __restrict__ lpart)
{
    extern __shared__ __align__(128) char smem[];
    uint32_t sb = (uint32_t)__cvta_generic_to_shared(smem);
    uint32_t Qb = sb;
    uint32_t Kb = sb + 32768;
    uint32_t Vb = sb + 98304;
    int t = threadIdx.x;
    int warp = t >> 5, lane = t & 31;
    int split = blockIdx.x;
    int m0 = blockIdx.y << 7;
    int j0base = split << 12;        // split * 4096

    // Q load (2 regions x 128 rows x 8 chunks = 2048)
#pragma unroll
    for (int i = 0; i < 8; i++) {
        int idx = t + (i << 8);
        int reg = idx >> 10, rem = idx & 1023;
        int row = rem >> 3, ch = rem & 7;
        uint32_t dst = Qb + reg * 16384 + row * 128 + ((ch ^ (row & 7)) << 4);
        cp16(dst, qb + (size_t)(m0 + row) * H + reg * 64 + ch * 8);
    }
    auto loadKV = [&](int it) {
        int b = it & 1;
        int j0 = j0base + (it << 7);
#pragma unroll
        for (int i = 0; i < 8; i++) {
            int idx = t + (i << 8);
            int reg = idx >> 10, rem = idx & 1023;
            int row = rem >> 3, ch = rem & 7;
            uint32_t sw = row * 128 + ((ch ^ (row & 7)) << 4);
            cp16(Kb + b * 32768 + reg * 16384 + sw,
                 kb + (size_t)(j0 + row) * H + reg * 64 + ch * 8);
            cp16(Vb + b * 32768 + reg * 16384 + sw,
                 vt + (size_t)row * L + j0 + reg * 64 + ch * 8);
        }
    };
    loadKV(0);
    asm volatile("cp.async.commit_group;\n");

    float acc_o[16][4];
#pragma unroll
    for (int nt = 0; nt < 16; nt++)
#pragma unroll
        for (int i = 0; i < 4; i++) acc_o[nt][i] = 0.f;
    float lsum0 = 0.f, lsum1 = 0.f;

    int rowpat = (lane & 7) + (((lane >> 3) & 1) << 3);
    int chA_hi = (lane >> 4) & 1;
    int rowB = (lane & 7) + ((lane >> 4) << 3);
    int chB_hi = (lane >> 3) & 1;
    int rA = (warp << 4) + rowpat;

    for (int it = 0; it < 32; it++) {
        if (it + 1 < 32) {
            loadKV(it + 1);
            asm volatile("cp.async.commit_group;\n");
            asm volatile("cp.async.wait_group 1;\n");
        } else {
            asm volatile("cp.async.wait_group 0;\n");
        }
        __syncthreads();
        int b = it & 1;

        // ---- S = Q @ K^T ----
        float accs[16][4];
#pragma unroll
        for (int nt = 0; nt < 16; nt++)
#pragma unroll
            for (int i = 0; i < 4; i++) accs[nt][i] = 0.f;

#pragma unroll
        for (int cr = 0; cr < 2; cr++) {
#pragma unroll
            for (int k16 = 0; k16 < 4; k16++) {
                int ch = (k16 << 1) + chA_hi;
                uint32_t afr[4];
                ldsm4(afr, Qb + cr * 16384 + rA * 128 + ((ch ^ (rA & 7)) << 4));
                int chb = (k16 << 1) + chB_hi;
#pragma unroll
                for (int nd = 0; nd < 8; nd++) {
                    int rB = (nd << 4) + rowB;
                    uint32_t bfr[4];
                    ldsm4(bfr, Kb + b * 32768 + cr * 16384 + rB * 128 + ((chb ^ (rB & 7)) << 4));
                    mma16816(accs[nd * 2],     afr, bfr[0], bfr[1]);
                    mma16816(accs[nd * 2 + 1], afr, bfr[2], bfr[3]);
                }
            }
        }

        // ---- P = exp(S) (no max shift), row sums, pack to bf16 A frags ----
        uint32_t pP[16][2];
#pragma unroll
        for (int nt = 0; nt < 16; nt++) {
            float e0 = __expf(accs[nt][0]);
            float e1 = __expf(accs[nt][1]);
            float e2 = __expf(accs[nt][2]);
            float e3 = __expf(accs[nt][3]);
            lsum0 += e0 + e1;
            lsum1 += e2 + e3;
            pP[nt][0] = packbf(e0, e1);
            pP[nt][1] = packbf(e2, e3);
        }

        // ---- O += P @ V ----
#pragma unroll
        for (int kk = 0; kk < 8; kk++) {
            uint32_t a[4] = {pP[kk*2][0], pP[kk*2][1], pP[kk*2+1][0], pP[kk*2+1][1]};
            int jr = kk >> 2;
            int chb = ((kk & 3) << 1) + chB_hi;
#pragma unroll
            for (int nd = 0; nd < 8; nd++) {
                int rB = (nd << 4) + rowB;
                uint32_t bfr[4];
                ldsm4(bfr, Vb + b * 32768 + jr * 16384 + rB * 128 + ((chb ^ (rB & 7)) << 4));
                mma16816(acc_o[nd * 2],     a, bfr[0], bfr[1]);
                mma16816(acc_o[nd * 2 + 1], a, bfr[2], bfr[3]);
            }
        }
        __syncthreads();
    }

    // ---- epilogue: write O partial + l partial ----
    int g = lane >> 2, tq = lane & 3;
    int row0 = m0 + (warp << 4) + g;
    float* Op = Opart + (size_t)split * LH;
#pragma unroll
    for (int nt = 0; nt < 16; nt++) {
        int cc = (nt << 3) + (tq << 1);
        *reinterpret_cast<float2*>(Op + (size_t)row0 * H + cc) = make_float2(acc_o[nt][0], acc_o[nt][1]);
        *reinterpret_cast<float2*>(Op + (size_t)(row0 + 8) * H + cc) = make_float2(acc_o[nt][2], acc_o[nt][3]);
    }
    lsum0 += __shfl_xor_sync(0xffffffffu, lsum0, 1);
    lsum0 += __shfl_xor_sync(0xffffffffu, lsum0, 2);
    lsum1 += __shfl_xor_sync(0xffffffffu, lsum1, 1);
    lsum1 += __shfl_xor_sync(0xffffffffu, lsum1, 2);
    if (tq == 0) {
        lpart[split * L + row0] = lsum0;
        lpart[split * L + row0 + 8] = lsum1;
    }
}

// ---------------- combine flash partials: h += (O0+O1)/(l0+l1) ----------------
__global__ void fa_combine_kernel(const float* __restrict__ Op,
                                  const float* __restrict__ lp,
                                  float* __restrict__ h) {
    int idx = blockIdx.x * 256 + threadIdx.x;
    int row = idx >> 7;
    float l = lp[row] + lp[L + row];
    h[idx] += (Op[idx] + Op[LH + idx]) / l;
}

// ---------------- V transpose [L][H] fp32 -> [H][L] bf16 ----------------
__global__ void transpose_bf16_kernel(const float* __restrict__ in,
                                      __nv_bfloat16* __restrict__ out) {
    __shared__ float tile[32][33];
    int j0 = blockIdx.x * 32, d0 = blockIdx.y * 32;
    int tx = threadIdx.x, ty = threadIdx.y;
#pragma unroll
    for (int i = 0; i < 4; i++) {
        int jj = ty + i * 8;
        tile[jj][tx] = in[(size_t)(j0 + jj) * H + d0 + tx];
    }
    __syncthreads();
#pragma unroll
    for (int i = 0; i < 4; i++) {
        int dd = ty + i * 8;
        out[(size_t)(d0 + dd) * L + j0 + tx] = __float2bfloat16_rn(tile[tx][dd]);
    }
}

// ---------------- launch ----------------
extern "C" void kernel_launch(void* const* d_in, const int* in_sizes, int n_in,
                              void* d_out, int out_size) {
    const float* x      = (const float*)d_in[0];
    const float* conv_w = (const float*)d_in[1];
    const float* conv_b = (const float*)d_in[2];
    const float* Wq     = (const float*)d_in[3];
    const float* bq     = (const float*)d_in[4];
    const float* Wk     = (const float*)d_in[5];
    const float* bk     = (const float*)d_in[6];
    const float* Wv     = (const float*)d_in[7];
    const float* bv     = (const float*)d_in[8];
    const float* Wff    = (const float*)d_in[9];
    const float* bff    = (const float*)d_in[10];
    float* out = (float*)d_out;

    float *p_h, *p_n, *p_v, *p_Op, *p_lp;
    __nv_bfloat16 *p_nh, *p_nl, *p_wh, *p_wl, *p_qb, *p_kb, *p_vtb;
    cudaGetSymbolAddress((void**)&p_h,   g_h);
    cudaGetSymbolAddress((void**)&p_n,   g_n);
    cudaGetSymbolAddress((void**)&p_v,   g_v);
    cudaGetSymbolAddress((void**)&p_Op,  g_Opart);
    cudaGetSymbolAddress((void**)&p_lp,  g_lp);
    cudaGetSymbolAddress((void**)&p_nh,  g_nh);
    cudaGetSymbolAddress((void**)&p_nl,  g_nl);
    cudaGetSymbolAddress((void**)&p_wh,  g_wh);
    cudaGetSymbolAddress((void**)&p_wl,  g_wl);
    cudaGetSymbolAddress((void**)&p_qb,  g_qb);
    cudaGetSymbolAddress((void**)&p_kb,  g_kb);
    cudaGetSymbolAddress((void**)&p_vtb, g_vtb);

    static int s_attr_done = 0;
    if (!s_attr_done) {
        cudaFuncSetAttribute(conv_tc_kernel, cudaFuncAttributeMaxDynamicSharedMemorySize, CONV_SMEM);
        cudaFuncSetAttribute(flash_kernel, cudaFuncAttributeMaxDynamicSharedMemorySize, FA_SMEM);
        s_attr_done = 1;
    }

    const float scale = 0.08838834764831845f;  // 1/sqrt(128)

    prep_w_kernel<<<1792, 256>>>(conv_w, p_wh, p_wl);
    posenc_kernel<<<4096, 256>>>(x, p_h);

    for (int ic = 0; ic < NC; ic++) {
        ln_split_kernel<<<1024, 256>>>(p_h, p_nh, p_nl);
        conv_tc_kernel<<<256, 256, CONV_SMEM>>>(p_nh, p_nl,
                                                p_wh + (size_t)ic * KS * H * H,
                                                p_wl + (size_t)ic * KS * H * H,
                                                conv_b + ic * H, p_h);
    }

    // attention
    ln_kernel<<<1024, 256>>>(p_h, p_n);
    gemm_nt_kernel<<<dim3(2, 128), 256>>>(p_n, Wq, bq, nullptr, p_qb, L, H, H, scale, 0, 1);
    gemm_nt_kernel<<<dim3(2, 128), 256>>>(p_n, Wk, bk, nullptr, p_kb, L, H, H, 1.f, 0, 1);
    gemm_nt_kernel<<<dim3(2, 128), 256>>>(p_n, Wv, bv, nullptr, p_v,  L, H, H, 1.f, 0, 0);
    transpose_bf16_kernel<<<dim3(256, 4), dim3(32, 8)>>>(p_v, p_vtb);

    flash_kernel<<<dim3(2, 64), 256, FA_SMEM>>>(p_qb, p_kb, p_vtb, p_Op, p_lp);
    fa_combine_kernel<<<4096, 256>>>(p_Op, p_lp, p_h);

    // feed-forward
    ln_kernel<<<1024, 256>>>(p_h, p_n);
    gemm_nt_kernel<<<dim3(2, 128), 256>>>(p_n, Wff, bff, p_h, out, L, H, H, 1.f, 1, 0);
}

// round 5
// speedup vs baseline: 6.3844x; 1.0774x over previous
#include <cuda_runtime.h>
#include <cuda_bf16.h>
#include <math.h>
#include <stdint.h>

#define L 8192
#define H 128
#define NC 4
#define KS 7
#define LH (L*H)

// ---------------- scratch (static device memory) ----------------
__device__ float g_h [LH];
__device__ float g_v [LH];
__device__ float g_Opart[4*LH];                // flash O partials (4 KV splits)
__device__ float g_lp[4*L];                    // flash l partials
__device__ __nv_bfloat16 g_nh[LH];             // LN out hi (bf16)
__device__ __nv_bfloat16 g_nl[LH];             // LN out lo (bf16)
__device__ __nv_bfloat16 g_wh[NC*KS*H*H];      // conv W hi [ic][k][o][c]
__device__ __nv_bfloat16 g_wl[NC*KS*H*H];      // conv W lo
__device__ __nv_bfloat16 g_pwh[4*H*H];         // proj W hi [mat][o][c] (q,k,v,ff)
__device__ __nv_bfloat16 g_pwl[4*H*H];         // proj W lo
__device__ __nv_bfloat16 g_qb[LH];
__device__ __nv_bfloat16 g_kb[LH];
__device__ __nv_bfloat16 g_vtb[LH];            // V^T [H][L] bf16

// ================= helpers =================
__device__ __forceinline__ void cp16(uint32_t dst, const void* src) {
    asm volatile("cp.async.cg.shared.global [%0], [%1], 16;\n" :: "r"(dst), "l"(src));
}
__device__ __forceinline__ void ldsm4(uint32_t* r, uint32_t addr) {
    asm volatile("ldmatrix.sync.aligned.m8n8.x4.shared.b16 {%0,%1,%2,%3}, [%4];"
        : "=r"(r[0]), "=r"(r[1]), "=r"(r[2]), "=r"(r[3]) : "r"(addr));
}
__device__ __forceinline__ void mma16816(float* c, const uint32_t* a, uint32_t b0, uint32_t b1) {
    asm volatile("mma.sync.aligned.m16n8k16.row.col.f32.bf16.bf16.f32 "
        "{%0,%1,%2,%3}, {%4,%5,%6,%7}, {%8,%9}, {%0,%1,%2,%3};"
        : "+f"(c[0]), "+f"(c[1]), "+f"(c[2]), "+f"(c[3])
        : "r"(a[0]), "r"(a[1]), "r"(a[2]), "r"(a[3]), "r"(b0), "r"(b1));
}
__device__ __forceinline__ uint32_t packbf(float a, float b) {
    __nv_bfloat162 p = __floats2bfloat162_rn(a, b);
    return *reinterpret_cast<uint32_t*>(&p);
}

// ---------------- positional encoding + add ----------------
__global__ void posenc_kernel(const float* __restrict__ x, float* __restrict__ h) {
    int idx = blockIdx.x * 256 + threadIdx.x;
    int l = idx >> 7, i = idx & 127;
    float di = (float)((i >> 1) << 1);
    float denom = powf(10000.0f, di * (1.0f / 128.0f));
    float ang = (float)l / denom;
    float pe = (i & 1) ? cosf(ang) : sinf(ang);
    h[idx] = x[idx] + pe;
}

// ---------------- layernorm with bf16 hi/lo split output ----------------
__global__ void ln_split_kernel(const float* __restrict__ in,
                                __nv_bfloat16* __restrict__ oh,
                                __nv_bfloat16* __restrict__ ol) {
    int warp = threadIdx.x >> 5, lane = threadIdx.x & 31;
    int row = blockIdx.x * 8 + warp;
    const float4* ip = reinterpret_cast<const float4*>(in + (size_t)row * H);
    float4 v = ip[lane];
    float s = v.x + v.y + v.z + v.w;
    float q = v.x*v.x + v.y*v.y + v.z*v.z + v.w*v.w;
#pragma unroll
    for (int o = 16; o > 0; o >>= 1) {
        s += __shfl_xor_sync(0xffffffffu, s, o);
        q += __shfl_xor_sync(0xffffffffu, q, o);
    }
    float mu  = s * (1.0f / H);
    float var = q * (1.0f / H) - mu * mu;
    float inv = rsqrtf(var + 1e-5f);
    float f[4] = {(v.x-mu)*inv, (v.y-mu)*inv, (v.z-mu)*inv, (v.w-mu)*inv};
    __nv_bfloat16 hi[4], lo[4];
#pragma unroll
    for (int i = 0; i < 4; i++) {
        hi[i] = __float2bfloat16_rn(f[i]);
        lo[i] = __float2bfloat16_rn(f[i] - __bfloat162float(hi[i]));
    }
    *reinterpret_cast<uint2*>(oh + (size_t)row * H + lane * 4) = *reinterpret_cast<uint2*>(hi);
    *reinterpret_cast<uint2*>(ol + (size_t)row * H + lane * 4) = *reinterpret_cast<uint2*>(lo);
}

// ---------------- conv weight prep ----------------
__global__ void prep_w_kernel(const float* __restrict__ w,
                              __nv_bfloat16* __restrict__ wh,
                              __nv_bfloat16* __restrict__ wl) {
    int idx = blockIdx.x * 256 + threadIdx.x;
    int c  = idx & 127;
    int o  = (idx >> 7) & 127;
    int t7 = idx >> 14;
    int k  = t7 % 7;
    int ic = t7 / 7;
    float v = w[(((size_t)ic * H + o) * H + c) * KS + k];
    __nv_bfloat16 hi = __float2bfloat16_rn(v);
    wh[idx] = hi;
    wl[idx] = __float2bfloat16_rn(v - __bfloat162float(hi));
}

// ---------------- projection weight prep: Wq/Wk/Wv/Wff -> hi/lo [mat][o][c] ----------------
__global__ void prep_pw_kernel(const float* __restrict__ Wq, const float* __restrict__ Wk,
                               const float* __restrict__ Wv, const float* __restrict__ Wff,
                               __nv_bfloat16* __restrict__ pwh, __nv_bfloat16* __restrict__ pwl) {
    int idx = blockIdx.x * 256 + threadIdx.x;      // 4*16384
    int mat = idx >> 14;
    int r = idx & 16383;
    const float* W = (mat == 0) ? Wq : (mat == 1) ? Wk : (mat == 2) ? Wv : Wff;
    float v = W[r];
    __nv_bfloat16 hi = __float2bfloat16_rn(v);
    pwh[idx] = hi;
    pwl[idx] = __float2bfloat16_rn(v - __bfloat162float(hi));
}

// ---------------- conv1d SAME (K=7) via tensor cores, bf16x3, 32 rows/block ----------------
#define CONV_SMEM (19456 + 65536)
__global__ __launch_bounds__(256) void conv_tc_kernel(
    const __nv_bfloat16* __restrict__ nh, const __nv_bfloat16* __restrict__ nl,
    const __nv_bfloat16* __restrict__ wh, const __nv_bfloat16* __restrict__ wl,
    const float* __restrict__ bias, float* __restrict__ h)
{
    extern __shared__ __align__(128) char smem[];
    uint32_t sb = (uint32_t)__cvta_generic_to_shared(smem);
    uint32_t Abase = sb;
    uint32_t Bbase = sb + 19456;
    int t = threadIdx.x;
    int m0 = blockIdx.x << 5;

    for (int i = t; i < 1216; i += 256) {
        int reg = i / 304;
        int rem = i - reg * 304;
        int r = rem >> 3, ch = rem & 7;
        int prec = reg >> 1, c64 = reg & 1;
        int gr = m0 - 3 + r;
        uint32_t off = reg * 4864 + r * 128 + ((ch ^ (r & 7)) << 4);
        if (gr >= 0 && gr < L) {
            const __nv_bfloat16* src = (prec ? nl : nh) + (size_t)gr * 128 + c64 * 64 + ch * 8;
            cp16(Abase + off, src);
        } else {
            *reinterpret_cast<uint4*>(smem + off) = make_uint4(0, 0, 0, 0);
        }
    }

    auto load_B = [&](int s) {
        int k = s >> 1, c64 = s & 1, buf = s & 1;
#pragma unroll
        for (int i = 0; i < 8; i++) {
            int idx = t + (i << 8);
            int prec = idx >> 10;
            int rem = idx & 1023;
            int o = rem >> 3, ch = rem & 7;
            const __nv_bfloat16* src = (prec ? wl : wh) + (size_t)(k * 128 + o) * 128 + c64 * 64 + ch * 8;
            uint32_t dst = Bbase + buf * 32768 + prec * 16384 + o * 128 + ((ch ^ (o & 7)) << 4);
            cp16(dst, src);
        }
    };

    int warp = t >> 5, lane = t & 31;
    int wm = warp >> 2, wn = warp & 3;

    float acc[4][4];
#pragma unroll
    for (int nt = 0; nt < 4; nt++)
#pragma unroll
        for (int i = 0; i < 4; i++) acc[nt][i] = 0.f;

    load_B(0);
    asm volatile("cp.async.commit_group;\n");

    int rowpat = (lane & 7) + (((lane >> 3) & 1) << 3);
    int chA_hi = (lane >> 4) & 1;
    int rowB = (lane & 7) + ((lane >> 4) << 3);
    int chB_hi = (lane >> 3) & 1;

    for (int s = 0; s < 14; s++) {
        if (s + 1 < 14) {
            load_B(s + 1);
            asm volatile("cp.async.commit_group;\n");
            asm volatile("cp.async.wait_group 1;\n");
        } else {
            asm volatile("cp.async.wait_group 0;\n");
        }
        __syncthreads();

        int k = s >> 1, c64 = s & 1;
        uint32_t Ahi = Abase + c64 * 4864;
        uint32_t Alo = Ahi + 9728;
        uint32_t Bh = Bbase + (s & 1) * 32768;
        uint32_t Bl = Bh + 16384;

#pragma unroll
        for (int k16 = 0; k16 < 4; k16++) {
            int ch = (k16 << 1) + chA_hi;
            int rA = (wm << 4) + rowpat + k;
            uint32_t aoff = rA * 128 + ((ch ^ (rA & 7)) << 4);
            uint32_t afr_h[4], afr_l[4];
            ldsm4(afr_h, Ahi + aoff);
            ldsm4(afr_l, Alo + aoff);

            int chb = (k16 << 1) + chB_hi;
            uint32_t bfr_h[2][4], bfr_l[2][4];
#pragma unroll
            for (int np = 0; np < 2; np++) {
                int rB = (wn << 5) + (np << 4) + rowB;
                uint32_t boff = rB * 128 + ((chb ^ (rB & 7)) << 4);
                ldsm4(bfr_h[np], Bh + boff);
                ldsm4(bfr_l[np], Bl + boff);
            }
#pragma unroll
            for (int nt = 0; nt < 4; nt++) {
                uint32_t b0h = bfr_h[nt >> 1][(nt & 1) << 1], b1h = bfr_h[nt >> 1][((nt & 1) << 1) + 1];
                uint32_t b0l = bfr_l[nt >> 1][(nt & 1) << 1], b1l = bfr_l[nt >> 1][((nt & 1) << 1) + 1];
                mma16816(acc[nt], afr_h, b0h, b1h);
                mma16816(acc[nt], afr_h, b0l, b1l);
                mma16816(acc[nt], afr_l, b0h, b1h);
            }
        }
        __syncthreads();
    }

    int g = lane >> 2, tq = lane & 3;
#pragma unroll
    for (int nt = 0; nt < 4; nt++) {
        int r = m0 + (wm << 4) + g;
        int cc = (wn << 5) + (nt << 3) + (tq << 1);
        float b0 = bias[cc], b1 = bias[cc + 1];
        float2 h0 = *reinterpret_cast<float2*>(h + (size_t)r * H + cc);
        float2 h1 = *reinterpret_cast<float2*>(h + (size_t)(r + 8) * H + cc);
        h0.x += acc[nt][0] + b0; h0.y += acc[nt][1] + b1;
        h1.x += acc[nt][2] + b0; h1.y += acc[nt][3] + b1;
        *reinterpret_cast<float2*>(h + (size_t)r * H + cc) = h0;
        *reinterpret_cast<float2*>(h + (size_t)(r + 8) * H + cc) = h1;
    }
}

// ---------------- bf16x3 TC projection GEMM: 64 rows x 128 cols, K=128 ----------------
// mode 0: QKV (blockIdx.x = matrix 0..2): q->bf16*scale, k->bf16, v->fp32
// mode 1: FF: out = relu(acc+bias)+resid (fp32)
#define PROJ_SMEM 98304
__global__ __launch_bounds__(256) void tc_proj_kernel(
    const __nv_bfloat16* __restrict__ ah, const __nv_bfloat16* __restrict__ al,
    const __nv_bfloat16* __restrict__ pwh, const __nv_bfloat16* __restrict__ pwl,
    const float* __restrict__ bq, const float* __restrict__ bk, const float* __restrict__ bv,
    __nv_bfloat16* __restrict__ out_q, __nv_bfloat16* __restrict__ out_k,
    float* __restrict__ out_v,
    float* __restrict__ out_ff, const float* __restrict__ resid,
    int mode, int matbase, float qscale)
{
    extern __shared__ __align__(128) char smem[];
    uint32_t sb = (uint32_t)__cvta_generic_to_shared(smem);
    int t = threadIdx.x;
    int mat = blockIdx.x + matbase;
    int m0 = blockIdx.y << 6;

    // A: 4 regions [prec][c64] of 64 rows x 128B = 8KB
#pragma unroll
    for (int i = 0; i < 8; i++) {
        int idx = t + (i << 8);              // 0..2047
        int reg = idx >> 9;
        int prec = reg >> 1, c64 = reg & 1;
        int row = (idx & 511) >> 3, ch = idx & 7;
        uint32_t dst = sb + reg * 8192 + row * 128 + ((ch ^ (row & 7)) << 4);
        cp16(dst, (prec ? al : ah) + (size_t)(m0 + row) * 128 + c64 * 64 + ch * 8);
    }
    // B: 4 regions [prec][c64] of 128 rows x 128B = 16KB, at sb+32768
#pragma unroll
    for (int i = 0; i < 16; i++) {
        int idx = t + (i << 8);              // 0..4095
        int reg = idx >> 10;
        int prec = reg >> 1, c64 = reg & 1;
        int row = (idx & 1023) >> 3, ch = idx & 7;
        uint32_t dst = sb + 32768 + reg * 16384 + row * 128 + ((ch ^ (row & 7)) << 4);
        cp16(dst, (prec ? pwl : pwh) + (size_t)mat * 16384 + (size_t)row * 128 + c64 * 64 + ch * 8);
    }
    asm volatile("cp.async.commit_group;\n");
    asm volatile("cp.async.wait_group 0;\n");
    __syncthreads();

    int warp = t >> 5, lane = t & 31;
    int wm = warp >> 2, wn = warp & 3;
    int rowpat = (lane & 7) + (((lane >> 3) & 1) << 3);
    int chA_hi = (lane >> 4) & 1;
    int rowB = (lane & 7) + ((lane >> 4) << 3);
    int chB_hi = (lane >> 3) & 1;

    float acc[2][4][4];
#pragma unroll
    for (int mt = 0; mt < 2; mt++)
#pragma unroll
        for (int nt = 0; nt < 4; nt++)
#pragma unroll
            for (int i = 0; i < 4; i++) acc[mt][nt][i] = 0.f;

#pragma unroll
    for (int k16 = 0; k16 < 8; k16++) {
        int cr = k16 >> 2, kk = k16 & 3;
        int ch = (kk << 1) + chA_hi;
        uint32_t afr_h[2][4], afr_l[2][4];
#pragma unroll
        for (int mt = 0; mt < 2; mt++) {
            int rA = (wm << 5) + (mt << 4) + rowpat;
            uint32_t aoff = rA * 128 + ((ch ^ (rA & 7)) << 4);
            ldsm4(afr_h[mt], sb + cr * 8192 + aoff);
            ldsm4(afr_l[mt], sb + 16384 + cr * 8192 + aoff);
        }
        int chb = (kk << 1) + chB_hi;
        uint32_t bfr_h[2][4], bfr_l[2][4];
#pragma unroll
        for (int np = 0; np < 2; np++) {
            int rB = (wn << 5) + (np << 4) + rowB;
            uint32_t boff = rB * 128 + ((chb ^ (rB & 7)) << 4);
            ldsm4(bfr_h[np], sb + 32768 + cr * 16384 + boff);
            ldsm4(bfr_l[np], sb + 65536 + cr * 16384 + boff);
        }
#pragma unroll
        for (int mt = 0; mt < 2; mt++)
#pragma unroll
            for (int nt = 0; nt < 4; nt++) {
                uint32_t b0h = bfr_h[nt >> 1][(nt & 1) << 1], b1h = bfr_h[nt >> 1][((nt & 1) << 1) + 1];
                uint32_t b0l = bfr_l[nt >> 1][(nt & 1) << 1], b1l = bfr_l[nt >> 1][((nt & 1) << 1) + 1];
                mma16816(acc[mt][nt], afr_h[mt], b0h, b1h);
                mma16816(acc[mt][nt], afr_h[mt], b0l, b1l);
                mma16816(acc[mt][nt], afr_l[mt], b0h, b1h);
            }
    }

    int g = lane >> 2, tq = lane & 3;
    const float* bias = (mode == 1) ? bq : (mat == 0 ? bq : (mat == 1 ? bk : bv));
#pragma unroll
    for (int mt = 0; mt < 2; mt++) {
#pragma unroll
        for (int nt = 0; nt < 4; nt++) {
            int r = m0 + (wm << 5) + (mt << 4) + g;
            int c = (wn << 5) + (nt << 3) + (tq << 1);
            float b0 = bias[c], b1 = bias[c + 1];
            float v0 = acc[mt][nt][0] + b0, v1 = acc[mt][nt][1] + b1;
            float v2 = acc[mt][nt][2] + b0, v3 = acc[mt][nt][3] + b1;
            size_t ci0 = (size_t)r * H + c, ci1 = (size_t)(r + 8) * H + c;
            if (mode == 1) {
                float2 r0 = *reinterpret_cast<const float2*>(resid + ci0);
                float2 r1 = *reinterpret_cast<const float2*>(resid + ci1);
                *reinterpret_cast<float2*>(out_ff + ci0) =
                    make_float2(fmaxf(v0, 0.f) + r0.x, fmaxf(v1, 0.f) + r0.y);
                *reinterpret_cast<float2*>(out_ff + ci1) =
                    make_float2(fmaxf(v2, 0.f) + r1.x, fmaxf(v3, 0.f) + r1.y);
            } else if (mat == 0) {
                *reinterpret_cast<uint32_t*>(out_q + ci0) = packbf(v0 * qscale, v1 * qscale);
                *reinterpret_cast<uint32_t*>(out_q + ci1) = packbf(v2 * qscale, v3 * qscale);
            } else if (mat == 1) {
                *reinterpret_cast<uint32_t*>(out_k + ci0) = packbf(v0, v1);
                *reinterpret_cast<uint32_t*>(out_k + ci1) = packbf(v2, v3);
            } else {
                *reinterpret_cast<float2*>(out_v + ci0) = make_float2(v0, v1);
                *reinterpret_cast<float2*>(out_v + ci1) = make_float2(v2, v3);
            }
        }
    }
}

// ---------------- fused flash attention, KV tiles of 64, 2 blocks/SM ----------------
// grid (4 kv-splits, 64 q-tiles), 256 threads = 8 warps x 16 Q rows.
// smem: Q 32KB + 2 x (K 16KB + V 16KB) = 96KB
#define FA_SMEM (32768 + 65536)
__global__ __launch_bounds__(256, 2) void flash_kernel(
    const __nv_bfloat16* __restrict__ qb,
    const __nv_bfloat16* __restrict__ kb,
    const __nv_bfloat16* __restrict__ vt,
    float* __restrict__ Opart, float* __restrict__ lpart)
{
    extern __shared__ __align__(128) char smem[];
    uint32_t sb = (uint32_t)__cvta_generic_to_shared(smem);
    uint32_t Qb = sb;
    uint32_t KVb = sb + 32768;
    int t = threadIdx.x;
    int warp = t >> 5, lane = t & 31;
    int split = blockIdx.x;
    int m0 = blockIdx.y << 7;
    int j0base = split << 11;        // split * 2048

    // Q load: 2 c64 regions of 128 rows x 128B
#pragma unroll
    for (int i = 0; i < 8; i++) {
        int idx = t + (i << 8);
        int reg = idx >> 10, rem = idx & 1023;
        int row = rem >> 3, ch = rem & 7;
        uint32_t dst = Qb + reg * 16384 + row * 128 + ((ch ^ (row & 7)) << 4);
        cp16(dst, qb + (size_t)(m0 + row) * H + reg * 64 + ch * 8);
    }
    auto loadKV = [&](int it) {
        int b = it & 1;
        int j0 = j0base + (it << 6);
        uint32_t base = KVb + b * 32768;
        // K: 64 rows, 2 c64 regions of 8KB
#pragma unroll
        for (int i = 0; i < 4; i++) {
            int idx = t + (i << 8);          // 0..1023
            int reg = idx >> 9, rem = idx & 511;
            int row = rem >> 3, ch = rem & 7;
            cp16(base + reg * 8192 + row * 128 + ((ch ^ (row & 7)) << 4),
                 kb + (size_t)(j0 + row) * H + reg * 64 + ch * 8);
        }
        // V^T: 128 d-rows x 64 l-cols (128B rows), at +16384
#pragma unroll
        for (int i = 0; i < 4; i++) {
            int idx = t + (i << 8);          // 0..1023
            int d = idx >> 3, ch = idx & 7;
            cp16(base + 16384 + d * 128 + ((ch ^ (d & 7)) << 4),
                 vt + (size_t)d * L + j0 + ch * 8);
        }
    };
    loadKV(0);
    asm volatile("cp.async.commit_group;\n");

    float acc_o[16][4];
#pragma unroll
    for (int nt = 0; nt < 16; nt++)
#pragma unroll
        for (int i = 0; i < 4; i++) acc_o[nt][i] = 0.f;
    float lsum0 = 0.f, lsum1 = 0.f;

    int rowpat = (lane & 7) + (((lane >> 3) & 1) << 3);
    int chA_hi = (lane >> 4) & 1;
    int rowB = (lane & 7) + ((lane >> 4) << 3);
    int chB_hi = (lane >> 3) & 1;
    int rA = (warp << 4) + rowpat;

    for (int it = 0; it < 32; it++) {
        if (it + 1 < 32) {
            loadKV(it + 1);
            asm volatile("cp.async.commit_group;\n");
            asm volatile("cp.async.wait_group 1;\n");
        } else {
            asm volatile("cp.async.wait_group 0;\n");
        }
        __syncthreads();
        int b = it & 1;
        uint32_t Kbase = KVb + b * 32768;
        uint32_t Vbase = Kbase + 16384;

        uint32_t pP[8][2];
        // S = Q @ K^T in two 32-col halves (keeps live regs low)
#pragma unroll
        for (int half = 0; half < 2; half++) {
            float accs[4][4];
#pragma unroll
            for (int nt = 0; nt < 4; nt++)
#pragma unroll
                for (int i = 0; i < 4; i++) accs[nt][i] = 0.f;
#pragma unroll
            for (int cr = 0; cr < 2; cr++) {
#pragma unroll
                for (int k16 = 0; k16 < 4; k16++) {
                    int ch = (k16 << 1) + chA_hi;
                    uint32_t afr[4];
                    ldsm4(afr, Qb + cr * 16384 + rA * 128 + ((ch ^ (rA & 7)) << 4));
                    int chb = (k16 << 1) + chB_hi;
#pragma unroll
                    for (int nd = 0; nd < 2; nd++) {
                        int rB = (half << 5) + (nd << 4) + rowB;
                        uint32_t bfr[4];
                        ldsm4(bfr, Kbase + cr * 8192 + rB * 128 + ((chb ^ (rB & 7)) << 4));
                        mma16816(accs[nd * 2],     afr, bfr[0], bfr[1]);
                        mma16816(accs[nd * 2 + 1], afr, bfr[2], bfr[3]);
                    }
                }
            }
#pragma unroll
            for (int nt = 0; nt < 4; nt++) {
                float e0 = __expf(accs[nt][0]);
                float e1 = __expf(accs[nt][1]);
                float e2 = __expf(accs[nt][2]);
                float e3 = __expf(accs[nt][3]);
                lsum0 += e0 + e1;
                lsum1 += e2 + e3;
                pP[half * 4 + nt][0] = packbf(e0, e1);
                pP[half * 4 + nt][1] = packbf(e2, e3);
            }
        }

        // O += P @ V  (k = 64 kv cols)
#pragma unroll
        for (int kk = 0; kk < 4; kk++) {
            uint32_t a[4] = {pP[kk*2][0], pP[kk*2][1], pP[kk*2+1][0], pP[kk*2+1][1]};
            int chb = (kk << 1) + chB_hi;
#pragma unroll
            for (int nd = 0; nd < 8; nd++) {
                int rB = (nd << 4) + rowB;
                uint32_t bfr[4];
                ldsm4(bfr, Vbase + rB * 128 + ((chb ^ (rB & 7)) << 4));
                mma16816(acc_o[nd * 2],     a, bfr[0], bfr[1]);
                mma16816(acc_o[nd * 2 + 1], a, bfr[2], bfr[3]);
            }
        }
        __syncthreads();
    }

    // epilogue: write O partial + l partial
    int g = lane >> 2, tq = lane & 3;
    int row0 = m0 + (warp << 4) + g;
    float* Op = Opart + (size_t)split * LH;
#pragma unroll
    for (int nt = 0; nt < 16; nt++) {
        int cc = (nt << 3) + (tq << 1);
        *reinterpret_cast<float2*>(Op + (size_t)row0 * H + cc) = make_float2(acc_o[nt][0], acc_o[nt][1]);
        *reinterpret_cast<float2*>(Op + (size_t)(row0 + 8) * H + cc) = make_float2(acc_o[nt][2], acc_o[nt][3]);
    }
    lsum0 += __shfl_xor_sync(0xffffffffu, lsum0, 1);
    lsum0 += __shfl_xor_sync(0xffffffffu, lsum0, 2);
    lsum1 += __shfl_xor_sync(0xffffffffu, lsum1, 1);
    lsum1 += __shfl_xor_sync(0xffffffffu, lsum1, 2);
    if (tq == 0) {
        lpart[split * L + row0] = lsum0;
        lpart[split * L + row0 + 8] = lsum1;
    }
}

// ---------------- combine flash partials: h += sum(O)/sum(l) ----------------
__global__ void fa_combine_kernel(const float* __restrict__ Op,
                                  const float* __restrict__ lp,
                                  float* __restrict__ h) {
    int idx = blockIdx.x * 256 + threadIdx.x;
    int row = idx >> 7;
    float l = lp[row] + lp[L + row] + lp[2*L + row] + lp[3*L + row];
    float o = Op[idx] + Op[LH + idx] + Op[2*LH + idx] + Op[3*LH + idx];
    h[idx] += o / l;
}

// ---------------- V transpose [L][H] fp32 -> [H][L] bf16 ----------------
__global__ void transpose_bf16_kernel(const float* __restrict__ in,
                                      __nv_bfloat16* __restrict__ out) {
    __shared__ float tile[32][33];
    int j0 = blockIdx.x * 32, d0 = blockIdx.y * 32;
    int tx = threadIdx.x, ty = threadIdx.y;
#pragma unroll
    for (int i = 0; i < 4; i++) {
        int jj = ty + i * 8;
        tile[jj][tx] = in[(size_t)(j0 + jj) * H + d0 + tx];
    }
    __syncthreads();
#pragma unroll
    for (int i = 0; i < 4; i++) {
        int dd = ty + i * 8;
        out[(size_t)(d0 + dd) * L + j0 + tx] = __float2bfloat16_rn(tile[tx][dd]);
    }
}

// ---------------- launch ----------------
extern "C" void kernel_launch(void* const* d_in, const int* in_sizes, int n_in,
                              void* d_out, int out_size) {
    const float* x      = (const float*)d_in[0];
    const float* conv_w = (const float*)d_in[1];
    const float* conv_b = (const float*)d_in[2];
    const float* Wq     = (const float*)d_in[3];
    const float* bq     = (const float*)d_in[4];
    const float* Wk     = (const float*)d_in[5];
    const float* bk     = (const float*)d_in[6];
    const float* Wv     = (const float*)d_in[7];
    const float* bv     = (const float*)d_in[8];
    const float* Wff    = (const float*)d_in[9];
    const float* bff    = (const float*)d_in[10];
    float* out = (float*)d_out;

    float *p_h, *p_v, *p_Op, *p_lp;
    __nv_bfloat16 *p_nh, *p_nl, *p_wh, *p_wl, *p_pwh, *p_pwl, *p_qb, *p_kb, *p_vtb;
    cudaGetSymbolAddress((void**)&p_h,   g_h);
    cudaGetSymbolAddress((void**)&p_v,   g_v);
    cudaGetSymbolAddress((void**)&p_Op,  g_Opart);
    cudaGetSymbolAddress((void**)&p_lp,  g_lp);
    cudaGetSymbolAddress((void**)&p_nh,  g_nh);
    cudaGetSymbolAddress((void**)&p_nl,  g_nl);
    cudaGetSymbolAddress((void**)&p_wh,  g_wh);
    cudaGetSymbolAddress((void**)&p_wl,  g_wl);
    cudaGetSymbolAddress((void**)&p_pwh, g_pwh);
    cudaGetSymbolAddress((void**)&p_pwl, g_pwl);
    cudaGetSymbolAddress((void**)&p_qb,  g_qb);
    cudaGetSymbolAddress((void**)&p_kb,  g_kb);
    cudaGetSymbolAddress((void**)&p_vtb, g_vtb);

    static int s_attr_done = 0;
    if (!s_attr_done) {
        cudaFuncSetAttribute(conv_tc_kernel, cudaFuncAttributeMaxDynamicSharedMemorySize, CONV_SMEM);
        cudaFuncSetAttribute(flash_kernel, cudaFuncAttributeMaxDynamicSharedMemorySize, FA_SMEM);
        cudaFuncSetAttribute(tc_proj_kernel, cudaFuncAttributeMaxDynamicSharedMemorySize, PROJ_SMEM);
        s_attr_done = 1;
    }

    const float scale = 0.08838834764831845f;  // 1/sqrt(128)

    prep_w_kernel<<<1792, 256>>>(conv_w, p_wh, p_wl);
    prep_pw_kernel<<<256, 256>>>(Wq, Wk, Wv, Wff, p_pwh, p_pwl);
    posenc_kernel<<<4096, 256>>>(x, p_h);

    for (int ic = 0; ic < NC; ic++) {
        ln_split_kernel<<<1024, 256>>>(p_h, p_nh, p_nl);
        conv_tc_kernel<<<256, 256, CONV_SMEM>>>(p_nh, p_nl,
                                                p_wh + (size_t)ic * KS * H * H,
                                                p_wl + (size_t)ic * KS * H * H,
                                                conv_b + ic * H, p_h);
    }

    // attention
    ln_split_kernel<<<1024, 256>>>(p_h, p_nh, p_nl);
    tc_proj_kernel<<<dim3(3, 128), 256, PROJ_SMEM>>>(
        p_nh, p_nl, p_pwh, p_pwl, bq, bk, bv,
        p_qb, p_kb, p_v, nullptr, nullptr, 0, 0, scale);
    transpose_bf16_kernel<<<dim3(256, 4), dim3(32, 8)>>>(p_v, p_vtb);

    flash_kernel<<<dim3(4, 64), 256, FA_SMEM>>>(p_qb, p_kb, p_vtb, p_Op, p_lp);
    fa_combine_kernel<<<4096, 256>>>(p_Op, p_lp, p_h);

    // feed-forward
    ln_split_kernel<<<1024, 256>>>(p_h, p_nh, p_nl);
    tc_proj_kernel<<<dim3(1, 128), 256, PROJ_SMEM>>>(
        p_nh, p_nl, p_pwh, p_pwl, bff, nullptr, nullptr,
        nullptr, nullptr, nullptr, out, p_h, 1, 3, 1.f);
}

// round 6
// speedup vs baseline: 6.6863x; 1.0473x over previous
#include <cuda_runtime.h>
#include <cuda_bf16.h>
#include <math.h>
#include <stdint.h>

#define L 8192
#define H 128
#define NC 4
#define KS 7
#define LH (L*H)

// ---------------- scratch (static device memory) ----------------
__device__ float g_h [LH];
__device__ float g_Opart[4*LH];                // flash O partials (4 KV splits)
__device__ float g_lp[4*L];                    // flash l partials
__device__ __nv_bfloat16 g_wh[NC*KS*H*H];      // conv W hi [ic][k][o][c]
__device__ __nv_bfloat16 g_wl[NC*KS*H*H];      // conv W lo
__device__ __nv_bfloat16 g_pwh[4*H*H];         // proj W hi [mat][o][c] (q,k,v,ff)
__device__ __nv_bfloat16 g_pwl[4*H*H];         // proj W lo
__device__ __nv_bfloat16 g_qb[LH];
__device__ __nv_bfloat16 g_kb[LH];
__device__ __nv_bfloat16 g_vtb[LH];            // V^T [H][L] bf16

// ================= helpers =================
__device__ __forceinline__ void cp16(uint32_t dst, const void* src) {
    asm volatile("cp.async.cg.shared.global [%0], [%1], 16;\n" :: "r"(dst), "l"(src));
}
__device__ __forceinline__ void ldsm4(uint32_t* r, uint32_t addr) {
    asm volatile("ldmatrix.sync.aligned.m8n8.x4.shared.b16 {%0,%1,%2,%3}, [%4];"
        : "=r"(r[0]), "=r"(r[1]), "=r"(r[2]), "=r"(r[3]) : "r"(addr));
}
__device__ __forceinline__ void mma16816(float* c, const uint32_t* a, uint32_t b0, uint32_t b1) {
    asm volatile("mma.sync.aligned.m16n8k16.row.col.f32.bf16.bf16.f32 "
        "{%0,%1,%2,%3}, {%4,%5,%6,%7}, {%8,%9}, {%0,%1,%2,%3};"
        : "+f"(c[0]), "+f"(c[1]), "+f"(c[2]), "+f"(c[3])
        : "r"(a[0]), "r"(a[1]), "r"(a[2]), "r"(a[3]), "r"(b0), "r"(b1));
}
__device__ __forceinline__ uint32_t packbf(float a, float b) {
    __nv_bfloat162 p = __floats2bfloat162_rn(a, b);
    return *reinterpret_cast<uint32_t*>(&p);
}

// In-warp LN of one row (lane owns 4 cols), produce hi/lo bf16 pairs.
__device__ __forceinline__ void ln_row(float4 v, uint32_t& hiA, uint32_t& hiB,
                                       uint32_t& loA, uint32_t& loB) {
    float s = v.x + v.y + v.z + v.w;
    float q = v.x*v.x + v.y*v.y + v.z*v.z + v.w*v.w;
#pragma unroll
    for (int o = 16; o > 0; o >>= 1) {
        s += __shfl_xor_sync(0xffffffffu, s, o);
        q += __shfl_xor_sync(0xffffffffu, q, o);
    }
    float mu  = s * (1.0f / H);
    float var = q * (1.0f / H) - mu * mu;
    float inv = rsqrtf(var + 1e-5f);
    float f0 = (v.x-mu)*inv, f1 = (v.y-mu)*inv, f2 = (v.z-mu)*inv, f3 = (v.w-mu)*inv;
    float h0 = __bfloat162float(__float2bfloat16_rn(f0));
    float h1 = __bfloat162float(__float2bfloat16_rn(f1));
    float h2 = __bfloat162float(__float2bfloat16_rn(f2));
    float h3 = __bfloat162float(__float2bfloat16_rn(f3));
    hiA = packbf(f0, f1); hiB = packbf(f2, f3);
    loA = packbf(f0 - h0, f1 - h1); loB = packbf(f2 - h2, f3 - h3);
}

// ---------------- positional encoding + add ----------------
__global__ void posenc_kernel(const float* __restrict__ x, float* __restrict__ h) {
    int idx = blockIdx.x * 256 + threadIdx.x;
    int l = idx >> 7, i = idx & 127;
    float di = (float)((i >> 1) << 1);
    float denom = powf(10000.0f, di * (1.0f / 128.0f));
    float ang = (float)l / denom;
    float pe = (i & 1) ? cosf(ang) : sinf(ang);
    h[idx] = x[idx] + pe;
}

// ---------------- conv weight prep ----------------
__global__ void prep_w_kernel(const float* __restrict__ w,
                              __nv_bfloat16* __restrict__ wh,
                              __nv_bfloat16* __restrict__ wl) {
    int idx = blockIdx.x * 256 + threadIdx.x;
    int c  = idx & 127;
    int o  = (idx >> 7) & 127;
    int t7 = idx >> 14;
    int k  = t7 % 7;
    int ic = t7 / 7;
    float v = w[(((size_t)ic * H + o) * H + c) * KS + k];
    __nv_bfloat16 hi = __float2bfloat16_rn(v);
    wh[idx] = hi;
    wl[idx] = __float2bfloat16_rn(v - __bfloat162float(hi));
}

// ---------------- projection weight prep ----------------
__global__ void prep_pw_kernel(const float* __restrict__ Wq, const float* __restrict__ Wk,
                               const float* __restrict__ Wv, const float* __restrict__ Wff,
                               __nv_bfloat16* __restrict__ pwh, __nv_bfloat16* __restrict__ pwl) {
    int idx = blockIdx.x * 256 + threadIdx.x;      // 4*16384
    int mat = idx >> 14;
    int r = idx & 16383;
    const float* W = (mat == 0) ? Wq : (mat == 1) ? Wk : (mat == 2) ? Wv : Wff;
    float v = W[r];
    __nv_bfloat16 hi = __float2bfloat16_rn(v);
    pwh[idx] = hi;
    pwl[idx] = __float2bfloat16_rn(v - __bfloat162float(hi));
}

// ---------------- conv1d SAME (K=7) via TC bf16x3, LN fused, 32 rows/block ----------------
// A smem: 4 regions [prec*2+c64] of 38 rows x 128B = 4864B each; B: 2 x 32768
#define CONV_SMEM (19456 + 65536)
__global__ __launch_bounds__(256) void conv_tc_kernel(
    const float* __restrict__ hin,
    const __nv_bfloat16* __restrict__ wh, const __nv_bfloat16* __restrict__ wl,
    const float* __restrict__ bias, float* __restrict__ h)
{
    extern __shared__ __align__(128) char smem[];
    uint32_t sb = (uint32_t)__cvta_generic_to_shared(smem);
    uint32_t Bbase = sb + 19456;
    int t = threadIdx.x;
    int m0 = blockIdx.x << 5;
    int warp = t >> 5, lane = t & 31;

    auto load_B = [&](int s) {
        int k = s >> 1, c64 = s & 1, buf = s & 1;
#pragma unroll
        for (int i = 0; i < 8; i++) {
            int idx = t + (i << 8);
            int prec = idx >> 10;
            int rem = idx & 1023;
            int o = rem >> 3, ch = rem & 7;
            const __nv_bfloat16* src = (prec ? wl : wh) + (size_t)(k * 128 + o) * 128 + c64 * 64 + ch * 8;
            uint32_t dst = Bbase + buf * 32768 + prec * 16384 + o * 128 + ((ch ^ (o & 7)) << 4);
            cp16(dst, src);
        }
    };

    load_B(0);
    asm volatile("cp.async.commit_group;\n");

    // ---- LN(h) rows m0-3..m0+34 -> hi/lo A regions (STS) ----
    {
        int c64 = lane >> 4;
        int ch = (lane & 15) >> 1;
        int sub = (lane & 1) << 3;
        for (int r = warp; r < 38; r += 8) {
            int gr = m0 - 3 + r;
            float4 v = make_float4(0.f, 0.f, 0.f, 0.f);
            if (gr >= 0 && gr < L)
                v = *reinterpret_cast<const float4*>(hin + (size_t)gr * H + lane * 4);
            uint32_t hiA, hiB, loA, loB;
            ln_row(v, hiA, hiB, loA, loB);
            uint32_t off = r * 128 + ((ch ^ (r & 7)) << 4) + sub;
            *reinterpret_cast<uint2*>(smem + c64 * 4864 + off) = make_uint2(hiA, hiB);
            *reinterpret_cast<uint2*>(smem + (2 + c64) * 4864 + off) = make_uint2(loA, loB);
        }
    }

    int wm = warp >> 2, wn = warp & 3;
    float acc[4][4];
#pragma unroll
    for (int nt = 0; nt < 4; nt++)
#pragma unroll
        for (int i = 0; i < 4; i++) acc[nt][i] = 0.f;

    int rowpat = (lane & 7) + (((lane >> 3) & 1) << 3);
    int chA_hi = (lane >> 4) & 1;
    int rowB = (lane & 7) + ((lane >> 4) << 3);
    int chB_hi = (lane >> 3) & 1;

    for (int s = 0; s < 14; s++) {
        if (s + 1 < 14) {
            load_B(s + 1);
            asm volatile("cp.async.commit_group;\n");
            asm volatile("cp.async.wait_group 1;\n");
        } else {
            asm volatile("cp.async.wait_group 0;\n");
        }
        __syncthreads();

        int k = s >> 1, c64 = s & 1;
        uint32_t Ahi = sb + c64 * 4864;
        uint32_t Alo = Ahi + 9728;
        uint32_t Bh = Bbase + (s & 1) * 32768;
        uint32_t Bl = Bh + 16384;

#pragma unroll
        for (int k16 = 0; k16 < 4; k16++) {
            int ch = (k16 << 1) + chA_hi;
            int rA = (wm << 4) + rowpat + k;
            uint32_t aoff = rA * 128 + ((ch ^ (rA & 7)) << 4);
            uint32_t afr_h[4], afr_l[4];
            ldsm4(afr_h, Ahi + aoff);
            ldsm4(afr_l, Alo + aoff);

            int chb = (k16 << 1) + chB_hi;
            uint32_t bfr_h[2][4], bfr_l[2][4];
#pragma unroll
            for (int np = 0; np < 2; np++) {
                int rB = (wn << 5) + (np << 4) + rowB;
                uint32_t boff = rB * 128 + ((chb ^ (rB & 7)) << 4);
                ldsm4(bfr_h[np], Bh + boff);
                ldsm4(bfr_l[np], Bl + boff);
            }
#pragma unroll
            for (int nt = 0; nt < 4; nt++) {
                uint32_t b0h = bfr_h[nt >> 1][(nt & 1) << 1], b1h = bfr_h[nt >> 1][((nt & 1) << 1) + 1];
                uint32_t b0l = bfr_l[nt >> 1][(nt & 1) << 1], b1l = bfr_l[nt >> 1][((nt & 1) << 1) + 1];
                mma16816(acc[nt], afr_h, b0h, b1h);
                mma16816(acc[nt], afr_h, b0l, b1l);
                mma16816(acc[nt], afr_l, b0h, b1h);
            }
        }
        __syncthreads();
    }

    int g = lane >> 2, tq = lane & 3;
#pragma unroll
    for (int nt = 0; nt < 4; nt++) {
        int r = m0 + (wm << 4) + g;
        int cc = (wn << 5) + (nt << 3) + (tq << 1);
        float b0 = bias[cc], b1 = bias[cc + 1];
        float2 h0 = *reinterpret_cast<float2*>(h + (size_t)r * H + cc);
        float2 h1 = *reinterpret_cast<float2*>(h + (size_t)(r + 8) * H + cc);
        h0.x += acc[nt][0] + b0; h0.y += acc[nt][1] + b1;
        h1.x += acc[nt][2] + b0; h1.y += acc[nt][3] + b1;
        *reinterpret_cast<float2*>(h + (size_t)r * H + cc) = h0;
        *reinterpret_cast<float2*>(h + (size_t)(r + 8) * H + cc) = h1;
    }
}

// ---------------- bf16x3 TC projection GEMM with fused LN: 64 rows x 128 cols ----------------
// mode 0: QKV (blockIdx.x = mat 0..2): q->bf16*scale, k->bf16, v->V^T bf16
// mode 1: FF: out = relu(acc+bias)+resid (fp32)
#define PROJ_SMEM 98304
__global__ __launch_bounds__(256) void tc_proj_kernel(
    const float* __restrict__ hin,
    const __nv_bfloat16* __restrict__ pwh, const __nv_bfloat16* __restrict__ pwl,
    const float* __restrict__ bq, const float* __restrict__ bk, const float* __restrict__ bv,
    __nv_bfloat16* __restrict__ out_q, __nv_bfloat16* __restrict__ out_k,
    __nv_bfloat16* __restrict__ out_vt,
    float* __restrict__ out_ff, const float* __restrict__ resid,
    int mode, int matbase, float qscale)
{
    extern __shared__ __align__(128) char smem[];
    uint32_t sb = (uint32_t)__cvta_generic_to_shared(smem);
    int t = threadIdx.x;
    int mat = blockIdx.x + matbase;
    int m0 = blockIdx.y << 6;
    int warp = t >> 5, lane = t & 31;

    // B: 4 regions [prec*2+c64] of 128 rows x 128B = 16KB, at sb+32768
#pragma unroll
    for (int i = 0; i < 16; i++) {
        int idx = t + (i << 8);              // 0..4095
        int reg = idx >> 10;
        int prec = reg >> 1, c64 = reg & 1;
        int row = (idx & 1023) >> 3, ch = idx & 7;
        uint32_t dst = sb + 32768 + reg * 16384 + row * 128 + ((ch ^ (row & 7)) << 4);
        cp16(dst, (prec ? pwl : pwh) + (size_t)mat * 16384 + (size_t)row * 128 + c64 * 64 + ch * 8);
    }
    asm volatile("cp.async.commit_group;\n");

    // ---- LN(h) rows m0..m0+63 -> hi/lo A regions (STS), overlapped with B cp.async ----
    {
        int c64 = lane >> 4;
        int ch = (lane & 15) >> 1;
        int sub = (lane & 1) << 3;
#pragma unroll
        for (int rr = 0; rr < 8; rr++) {
            int r = warp + (rr << 3);
            float4 v = *reinterpret_cast<const float4*>(hin + (size_t)(m0 + r) * H + lane * 4);
            uint32_t hiA, hiB, loA, loB;
            ln_row(v, hiA, hiB, loA, loB);
            uint32_t off = r * 128 + ((ch ^ (r & 7)) << 4) + sub;
            *reinterpret_cast<uint2*>(smem + c64 * 8192 + off) = make_uint2(hiA, hiB);
            *reinterpret_cast<uint2*>(smem + 16384 + c64 * 8192 + off) = make_uint2(loA, loB);
        }
    }
    asm volatile("cp.async.wait_group 0;\n");
    __syncthreads();

    int wm = warp >> 2, wn = warp & 3;
    int rowpat = (lane & 7) + (((lane >> 3) & 1) << 3);
    int chA_hi = (lane >> 4) & 1;
    int rowB = (lane & 7) + ((lane >> 4) << 3);
    int chB_hi = (lane >> 3) & 1;

    float acc[2][4][4];
#pragma unroll
    for (int mt = 0; mt < 2; mt++)
#pragma unroll
        for (int nt = 0; nt < 4; nt++)
#pragma unroll
            for (int i = 0; i < 4; i++) acc[mt][nt][i] = 0.f;

#pragma unroll
    for (int k16 = 0; k16 < 8; k16++) {
        int cr = k16 >> 2, kk = k16 & 3;
        int ch = (kk << 1) + chA_hi;
        uint32_t afr_h[2][4], afr_l[2][4];
#pragma unroll
        for (int mt = 0; mt < 2; mt++) {
            int rA = (wm << 5) + (mt << 4) + rowpat;
            uint32_t aoff = rA * 128 + ((ch ^ (rA & 7)) << 4);
            ldsm4(afr_h[mt], sb + cr * 8192 + aoff);
            ldsm4(afr_l[mt], sb + 16384 + cr * 8192 + aoff);
        }
        int chb = (kk << 1) + chB_hi;
        uint32_t bfr_h[2][4], bfr_l[2][4];
#pragma unroll
        for (int np = 0; np < 2; np++) {
            int rB = (wn << 5) + (np << 4) + rowB;
            uint32_t boff = rB * 128 + ((chb ^ (rB & 7)) << 4);
            ldsm4(bfr_h[np], sb + 32768 + cr * 16384 + boff);
            ldsm4(bfr_l[np], sb + 65536 + cr * 16384 + boff);
        }
#pragma unroll
        for (int mt = 0; mt < 2; mt++)
#pragma unroll
            for (int nt = 0; nt < 4; nt++) {
                uint32_t b0h = bfr_h[nt >> 1][(nt & 1) << 1], b1h = bfr_h[nt >> 1][((nt & 1) << 1) + 1];
                uint32_t b0l = bfr_l[nt >> 1][(nt & 1) << 1], b1l = bfr_l[nt >> 1][((nt & 1) << 1) + 1];
                mma16816(acc[mt][nt], afr_h[mt], b0h, b1h);
                mma16816(acc[mt][nt], afr_h[mt], b0l, b1l);
                mma16816(acc[mt][nt], afr_l[mt], b0h, b1h);
            }
    }

    int g = lane >> 2, tq = lane & 3;
    const float* bias = (mode == 1) ? bq : (mat == 0 ? bq : (mat == 1 ? bk : bv));
#pragma unroll
    for (int mt = 0; mt < 2; mt++) {
#pragma unroll
        for (int nt = 0; nt < 4; nt++) {
            int r = m0 + (wm << 5) + (mt << 4) + g;
            int c = (wn << 5) + (nt << 3) + (tq << 1);
            float b0 = bias[c], b1 = bias[c + 1];
            float v0 = acc[mt][nt][0] + b0, v1 = acc[mt][nt][1] + b1;
            float v2 = acc[mt][nt][2] + b0, v3 = acc[mt][nt][3] + b1;
            size_t ci0 = (size_t)r * H + c, ci1 = (size_t)(r + 8) * H + c;
            if (mode == 1) {
                float2 r0 = *reinterpret_cast<const float2*>(resid + ci0);
                float2 r1 = *reinterpret_cast<const float2*>(resid + ci1);
                *reinterpret_cast<float2*>(out_ff + ci0) =
                    make_float2(fmaxf(v0, 0.f) + r0.x, fmaxf(v1, 0.f) + r0.y);
                *reinterpret_cast<float2*>(out_ff + ci1) =
                    make_float2(fmaxf(v2, 0.f) + r1.x, fmaxf(v3, 0.f) + r1.y);
            } else if (mat == 0) {
                *reinterpret_cast<uint32_t*>(out_q + ci0) = packbf(v0 * qscale, v1 * qscale);
                *reinterpret_cast<uint32_t*>(out_q + ci1) = packbf(v2 * qscale, v3 * qscale);
            } else if (mat == 1) {
                *reinterpret_cast<uint32_t*>(out_k + ci0) = packbf(v0, v1);
                *reinterpret_cast<uint32_t*>(out_k + ci1) = packbf(v2, v3);
            } else {
                // V: write transposed bf16 [H][L]
                out_vt[(size_t)c * L + r]           = __float2bfloat16_rn(v0);
                out_vt[(size_t)(c + 1) * L + r]     = __float2bfloat16_rn(v1);
                out_vt[(size_t)c * L + r + 8]       = __float2bfloat16_rn(v2);
                out_vt[(size_t)(c + 1) * L + r + 8] = __float2bfloat16_rn(v3);
            }
        }
    }
}

// ---------------- fused flash attention, KV tiles of 64, 2 blocks/SM ----------------
#define FA_SMEM (32768 + 65536)
__global__ __launch_bounds__(256, 2) void flash_kernel(
    const __nv_bfloat16* __restrict__ qb,
    const __nv_bfloat16* __restrict__ kb,
    const __nv_bfloat16* __restrict__ vt,
    float* __restrict__ Opart, float* __restrict__ lpart)
{
    extern __shared__ __align__(128) char smem[];
    uint32_t sb = (uint32_t)__cvta_generic_to_shared(smem);
    uint32_t Qb = sb;
    uint32_t KVb = sb + 32768;
    int t = threadIdx.x;
    int warp = t >> 5, lane = t & 31;
    int split = blockIdx.x;
    int m0 = blockIdx.y << 7;
    int j0base = split << 11;

#pragma unroll
    for (int i = 0; i < 8; i++) {
        int idx = t + (i << 8);
        int reg = idx >> 10, rem = idx & 1023;
        int row = rem >> 3, ch = rem & 7;
        uint32_t dst = Qb + reg * 16384 + row * 128 + ((ch ^ (row & 7)) << 4);
        cp16(dst, qb + (size_t)(m0 + row) * H + reg * 64 + ch * 8);
    }
    auto loadKV = [&](int it) {
        int b = it & 1;
        int j0 = j0base + (it << 6);
        uint32_t base = KVb + b * 32768;
#pragma unroll
        for (int i = 0; i < 4; i++) {
            int idx = t + (i << 8);
            int reg = idx >> 9, rem = idx & 511;
            int row = rem >> 3, ch = rem & 7;
            cp16(base + reg * 8192 + row * 128 + ((ch ^ (row & 7)) << 4),
                 kb + (size_t)(j0 + row) * H + reg * 64 + ch * 8);
        }
#pragma unroll
        for (int i = 0; i < 4; i++) {
            int idx = t + (i << 8);
            int d = idx >> 3, ch = idx & 7;
            cp16(base + 16384 + d * 128 + ((ch ^ (d & 7)) << 4),
                 vt + (size_t)d * L + j0 + ch * 8);
        }
    };
    loadKV(0);
    asm volatile("cp.async.commit_group;\n");

    float acc_o[16][4];
#pragma unroll
    for (int nt = 0; nt < 16; nt++)
#pragma unroll
        for (int i = 0; i < 4; i++) acc_o[nt][i] = 0.f;
    float lsum0 = 0.f, lsum1 = 0.f;

    int rowpat = (lane & 7) + (((lane >> 3) & 1) << 3);
    int chA_hi = (lane >> 4) & 1;
    int rowB = (lane & 7) + ((lane >> 4) << 3);
    int chB_hi = (lane >> 3) & 1;
    int rA = (warp << 4) + rowpat;

    for (int it = 0; it < 32; it++) {
        if (it + 1 < 32) {
            loadKV(it + 1);
            asm volatile("cp.async.commit_group;\n");
            asm volatile("cp.async.wait_group 1;\n");
        } else {
            asm volatile("cp.async.wait_group 0;\n");
        }
        __syncthreads();
        int b = it & 1;
        uint32_t Kbase = KVb + b * 32768;
        uint32_t Vbase = Kbase + 16384;

        uint32_t pP[8][2];
#pragma unroll
        for (int half = 0; half < 2; half++) {
            float accs[4][4];
#pragma unroll
            for (int nt = 0; nt < 4; nt++)
#pragma unroll
                for (int i = 0; i < 4; i++) accs[nt][i] = 0.f;
#pragma unroll
            for (int cr = 0; cr < 2; cr++) {
#pragma unroll
                for (int k16 = 0; k16 < 4; k16++) {
                    int ch = (k16 << 1) + chA_hi;
                    uint32_t afr[4];
                    ldsm4(afr, Qb + cr * 16384 + rA * 128 + ((ch ^ (rA & 7)) << 4));
                    int chb = (k16 << 1) + chB_hi;
#pragma unroll
                    for (int nd = 0; nd < 2; nd++) {
                        int rB = (half << 5) + (nd << 4) + rowB;
                        uint32_t bfr[4];
                        ldsm4(bfr, Kbase + cr * 8192 + rB * 128 + ((chb ^ (rB & 7)) << 4));
                        mma16816(accs[nd * 2],     afr, bfr[0], bfr[1]);
                        mma16816(accs[nd * 2 + 1], afr, bfr[2], bfr[3]);
                    }
                }
            }
#pragma unroll
            for (int nt = 0; nt < 4; nt++) {
                float e0 = __expf(accs[nt][0]);
                float e1 = __expf(accs[nt][1]);
                float e2 = __expf(accs[nt][2]);
                float e3 = __expf(accs[nt][3]);
                lsum0 += e0 + e1;
                lsum1 += e2 + e3;
                pP[half * 4 + nt][0] = packbf(e0, e1);
                pP[half * 4 + nt][1] = packbf(e2, e3);
            }
        }

#pragma unroll
        for (int kk = 0; kk < 4; kk++) {
            uint32_t a[4] = {pP[kk*2][0], pP[kk*2][1], pP[kk*2+1][0], pP[kk*2+1][1]};
            int chb = (kk << 1) + chB_hi;
#pragma unroll
            for (int nd = 0; nd < 8; nd++) {
                int rB = (nd << 4) + rowB;
                uint32_t bfr[4];
                ldsm4(bfr, Vbase + rB * 128 + ((chb ^ (rB & 7)) << 4));
                mma16816(acc_o[nd * 2],     a, bfr[0], bfr[1]);
                mma16816(acc_o[nd * 2 + 1], a, bfr[2], bfr[3]);
            }
        }
        __syncthreads();
    }

    int g = lane >> 2, tq = lane & 3;
    int row0 = m0 + (warp << 4) + g;
    float* Op = Opart + (size_t)split * LH;
#pragma unroll
    for (int nt = 0; nt < 16; nt++) {
        int cc = (nt << 3) + (tq << 1);
        *reinterpret_cast<float2*>(Op + (size_t)row0 * H + cc) = make_float2(acc_o[nt][0], acc_o[nt][1]);
        *reinterpret_cast<float2*>(Op + (size_t)(row0 + 8) * H + cc) = make_float2(acc_o[nt][2], acc_o[nt][3]);
    }
    lsum0 += __shfl_xor_sync(0xffffffffu, lsum0, 1);
    lsum0 += __shfl_xor_sync(0xffffffffu, lsum0, 2);
    lsum1 += __shfl_xor_sync(0xffffffffu, lsum1, 1);
    lsum1 += __shfl_xor_sync(0xffffffffu, lsum1, 2);
    if (tq == 0) {
        lpart[split * L + row0] = lsum0;
        lpart[split * L + row0 + 8] = lsum1;
    }
}

// ---------------- combine flash partials: h += sum(O)/sum(l) ----------------
__global__ void fa_combine_kernel(const float* __restrict__ Op,
                                  const float* __restrict__ lp,
                                  float* __restrict__ h) {
    int idx = blockIdx.x * 256 + threadIdx.x;
    int row = idx >> 7;
    float l = lp[row] + lp[L + row] + lp[2*L + row] + lp[3*L + row];
    float o = Op[idx] + Op[LH + idx] + Op[2*LH + idx] + Op[3*LH + idx];
    h[idx] += o / l;
}

// ---------------- launch ----------------
extern "C" void kernel_launch(void* const* d_in, const int* in_sizes, int n_in,
                              void* d_out, int out_size) {
    const float* x      = (const float*)d_in[0];
    const float* conv_w = (const float*)d_in[1];
    const float* conv_b = (const float*)d_in[2];
    const float* Wq     = (const float*)d_in[3];
    const float* bq     = (const float*)d_in[4];
    const float* Wk     = (const float*)d_in[5];
    const float* bk     = (const float*)d_in[6];
    const float* Wv     = (const float*)d_in[7];
    const float* bv     = (const float*)d_in[8];
    const float* Wff    = (const float*)d_in[9];
    const float* bff    = (const float*)d_in[10];
    float* out = (float*)d_out;

    float *p_h, *p_Op, *p_lp;
    __nv_bfloat16 *p_wh, *p_wl, *p_pwh, *p_pwl, *p_qb, *p_kb, *p_vtb;
    cudaGetSymbolAddress((void**)&p_h,   g_h);
    cudaGetSymbolAddress((void**)&p_Op,  g_Opart);
    cudaGetSymbolAddress((void**)&p_lp,  g_lp);
    cudaGetSymbolAddress((void**)&p_wh,  g_wh);
    cudaGetSymbolAddress((void**)&p_wl,  g_wl);
    cudaGetSymbolAddress((void**)&p_pwh, g_pwh);
    cudaGetSymbolAddress((void**)&p_pwl, g_pwl);
    cudaGetSymbolAddress((void**)&p_qb,  g_qb);
    cudaGetSymbolAddress((void**)&p_kb,  g_kb);
    cudaGetSymbolAddress((void**)&p_vtb, g_vtb);

    static int s_attr_done = 0;
    if (!s_attr_done) {
        cudaFuncSetAttribute(conv_tc_kernel, cudaFuncAttributeMaxDynamicSharedMemorySize, CONV_SMEM);
        cudaFuncSetAttribute(flash_kernel, cudaFuncAttributeMaxDynamicSharedMemorySize, FA_SMEM);
        cudaFuncSetAttribute(tc_proj_kernel, cudaFuncAttributeMaxDynamicSharedMemorySize, PROJ_SMEM);
        s_attr_done = 1;
    }

    const float scale = 0.08838834764831845f;  // 1/sqrt(128)

    prep_w_kernel<<<1792, 256>>>(conv_w, p_wh, p_wl);
    prep_pw_kernel<<<256, 256>>>(Wq, Wk, Wv, Wff, p_pwh, p_pwl);
    posenc_kernel<<<4096, 256>>>(x, p_h);

    for (int ic = 0; ic < NC; ic++) {
        conv_tc_kernel<<<256, 256, CONV_SMEM>>>(p_h,
                                                p_wh + (size_t)ic * KS * H * H,
                                                p_wl + (size_t)ic * KS * H * H,
                                                conv_b + ic * H, p_h);
    }

    // attention: QKV proj with fused LN; V written transposed bf16
    tc_proj_kernel<<<dim3(3, 128), 256, PROJ_SMEM>>>(
        p_h, p_pwh, p_pwl, bq, bk, bv,
        p_qb, p_kb, p_vtb, nullptr, nullptr, 0, 0, scale);

    flash_kernel<<<dim3(4, 64), 256, FA_SMEM>>>(p_qb, p_kb, p_vtb, p_Op, p_lp);
    fa_combine_kernel<<<4096, 256>>>(p_Op, p_lp, p_h);

    // feed-forward with fused LN
    tc_proj_kernel<<<dim3(1, 128), 256, PROJ_SMEM>>>(
        p_h, p_pwh, p_pwl, bff, nullptr, nullptr,
        nullptr, nullptr, nullptr, out, p_h, 1, 3, 1.f);
}